// round 9
// baseline (speedup 1.0000x reference)
#include <cuda_runtime.h>
#include <cuda_fp16.h>
#include <math.h>
#include <stdint.h>

#define H_DIM  512
#define NGRID  65536
#define NMESH  10242
#define NEDGE  131072

// ---------------- scratch (device globals: allocation-guard safe) ----------
__device__ __half g_e16[(size_t)NEDGE * H_DIM];   // edge feats fp16
__device__ __half g_g16[(size_t)NGRID * H_DIM];   // grid feats fp16
__device__ __half g_m16[(size_t)NMESH * H_DIM];   // mesh feats fp16
__device__ __half g_agg16[(size_t)NMESH * H_DIM]; // agg fp16
__device__ __half g_h16[(size_t)NEDGE * H_DIM];   // hidden fp16
__device__ float  g_y[(size_t)NEDGE * H_DIM];     // pre-LN output fp32
__device__ float  g_agg[(size_t)NMESH * H_DIM];   // segment-sum fp32
__device__ __half g_wt16[(size_t)512 * 4608];     // transposed weights fp16 [N, K]

#define OFF_WE1T 0
#define OFF_WN1T (512*1536)
#define OFF_WE2T (OFF_WN1T + 512*1024)
#define OFF_WN2T (OFF_WE2T + 512*512)
#define OFF_WG1T (OFF_WN2T + 512*512)
#define OFF_WG2T (OFF_WG1T + 512*512)

// Virtual concatenated fp16 A matrix: segment s covers cols [s*512,(s+1)*512)
struct AViewH {
    const __half* base0; const int* idx0;
    const __half* base1; const int* idx1;
    const __half* base2; const int* idx2;
};

__device__ __forceinline__ const __half* seg_row_ptr(const AViewH& A, int seg, int r) {
    const __half* b; const int* ix;
    if (seg == 0)      { b = A.base0; ix = A.idx0; }
    else if (seg == 1) { b = A.base1; ix = A.idx1; }
    else               { b = A.base2; ix = A.idx2; }
    int ar = ix ? ix[r] : r;
    return b + (size_t)ar * H_DIM;
}

__device__ __forceinline__ float silu(float x) { return x / (1.0f + expf(-x)); }

__device__ __forceinline__ uint32_t smem_u32(const void* p) {
    uint32_t a;
    asm("{ .reg .u64 t; cvta.to.shared.u64 t, %1; cvt.u32.u64 %0, t; }" : "=r"(a) : "l"(p));
    return a;
}
__device__ __forceinline__ void cpasync16(uint32_t s, const void* g) {
    asm volatile("cp.async.cg.shared.global [%0], [%1], 16;" :: "r"(s), "l"(g));
}
__device__ __forceinline__ void mma_f16(float* d, const uint32_t* a, const uint32_t* b) {
    asm volatile(
        "mma.sync.aligned.m16n8k16.row.col.f32.f16.f16.f32 "
        "{%0,%1,%2,%3}, {%4,%5,%6,%7}, {%8,%9}, {%0,%1,%2,%3};"
        : "+f"(d[0]), "+f"(d[1]), "+f"(d[2]), "+f"(d[3])
        : "r"(a[0]), "r"(a[1]), "r"(a[2]), "r"(a[3]), "r"(b[0]), "r"(b[1]));
}

// ---------------- fp16 tensor-core GEMM: C = act(A @ Wt^T + bias) -----------
// BM=128, BN=256, BK=32(halfs). 256 threads = 8 warps (2m x 4n), warp 64x64.
// LDS traffic halved vs 32x64 warp tile: 512 wavefronts/K-tile = mma floor.
#define BM 128
#define BN 256
#define SW  20
#define ATW (128 * SW)
#define BTW (256 * SW)
#define STW (ATW + BTW)
#define NSTG 4
#define SMEM_BYTES (NSTG * STW * 4)

template<int ACT, int OUT_HALF>
__global__ __launch_bounds__(256, 1)
void tc_gemm(AViewH A, const __half* __restrict__ Wt, const float* __restrict__ bias,
             void* __restrict__ Cv, int M, int K)
{
    extern __shared__ uint32_t smw[];

    const int tid = threadIdx.x, wid = tid >> 5, lane = tid & 31;
    const int g = lane >> 2, tc = lane & 3;
    const int wm = wid & 1, wn = wid >> 1;               // 2m x 4n warp grid
    const int row0 = wm * 64, col0 = wn * 64;
    const int bm = blockIdx.y * BM, bn = blockIdx.x * BN;

    // ---- loader mapping: thread t -> row t>>1, 16 halfs at (t&1)*16 (2 chunks)
    const int lr  = tid >> 1;         // 0..127
    const int lcH = (tid & 1) * 16;   // half offset
    int arow = bm + lr; if (arow >= M) arow = M - 1;
    const __half* rpa[3];
    rpa[0] = seg_row_ptr(A, 0, arow);
    rpa[1] = (K > 512)  ? seg_row_ptr(A, 1, arow) : rpa[0];
    rpa[2] = (K > 1024) ? seg_row_ptr(A, 2, arow) : rpa[0];
    const __half* bp0 = Wt + (size_t)(bn + lr) * K;
    const __half* bp1 = Wt + (size_t)(bn + lr + 128) * K;

    const uint32_t sbase = smem_u32(smw);
    const uint32_t aOff  = ((uint32_t)(lr * SW) + (uint32_t)(lcH >> 1)) * 4;
    const uint32_t bOff0 = aOff;
    const uint32_t bOff1 = ((uint32_t)((lr + 128) * SW) + (uint32_t)(lcH >> 1)) * 4;

    auto load_tile = [&](int kt, int slot) {
        const int seg = kt >> 9, kin = kt & 511;
        const uint32_t sA = sbase + (uint32_t)(slot * STW) * 4;
        const uint32_t sB = sA + (uint32_t)ATW * 4;
        const __half* ap = rpa[seg] + kin + lcH;
        cpasync16(sA + aOff,       ap);
        cpasync16(sA + aOff + 16,  ap + 8);
        const __half* b0 = bp0 + kt + lcH;
        cpasync16(sB + bOff0,      b0);
        cpasync16(sB + bOff0 + 16, b0 + 8);
        const __half* b1 = bp1 + kt + lcH;
        cpasync16(sB + bOff1,      b1);
        cpasync16(sB + bOff1 + 16, b1 + 8);
        asm volatile("cp.async.commit_group;");
    };

    float acc[4][8][4];
    #pragma unroll
    for (int i = 0; i < 4; i++)
        #pragma unroll
        for (int j = 0; j < 8; j++)
            #pragma unroll
            for (int e = 0; e < 4; e++) acc[i][j][e] = 0.0f;

    const int T = K >> 5;
    load_tile(0, 0);
    if (T > 1) load_tile(32, 1);
    if (T > 2) load_tile(64, 2);

    int slot = 0;
    for (int t = 0; t < T; ++t) {
        if      (t + 2 < T) asm volatile("cp.async.wait_group 2;");
        else if (t + 1 < T) asm volatile("cp.async.wait_group 1;");
        else                asm volatile("cp.async.wait_group 0;");
        __syncthreads();
        if (t + 3 < T) load_tile((t + 3) << 5, (slot + 3) & 3);

        const uint32_t* as = smw + slot * STW;
        const uint32_t* ws = as + ATW;
        #pragma unroll
        for (int kk = 0; kk < 2; kk++) {
            const int k0 = kk * 8;     // word offset of this k16 step
            uint32_t af[4][4], bf[8][2];
            #pragma unroll
            for (int mt = 0; mt < 4; mt++) {
                const int r = row0 + mt * 16 + g;
                const int b0 = r * SW + k0 + tc;
                af[mt][0] = as[b0];
                af[mt][1] = as[b0 + 8 * SW];
                af[mt][2] = as[b0 + 4];
                af[mt][3] = as[b0 + 8 * SW + 4];
            }
            #pragma unroll
            for (int nt = 0; nt < 8; nt++) {
                const int n = col0 + nt * 8 + g;
                const int b0 = n * SW + k0 + tc;
                bf[nt][0] = ws[b0];
                bf[nt][1] = ws[b0 + 4];
            }
            #pragma unroll
            for (int mt = 0; mt < 4; mt++)
                #pragma unroll
                for (int nt = 0; nt < 8; nt++)
                    mma_f16(acc[mt][nt], af[mt], bf[nt]);
        }
        slot = (slot + 1) & 3;
    }

    // ---- epilogue: bias + activation
    float bv[16];
    #pragma unroll
    for (int nt = 0; nt < 8; nt++) {
        bv[2 * nt]     = bias[bn + col0 + nt * 8 + 2 * tc];
        bv[2 * nt + 1] = bias[bn + col0 + nt * 8 + 2 * tc + 1];
    }
    #pragma unroll
    for (int mt = 0; mt < 4; mt++) {
        const int r0 = bm + row0 + mt * 16 + g;
        #pragma unroll
        for (int half = 0; half < 2; half++) {
            const int r = r0 + half * 8;
            if (r >= M) continue;
            #pragma unroll
            for (int nt = 0; nt < 8; nt++) {
                const int c = nt * 8 + 2 * tc;
                float x0 = acc[mt][nt][half * 2 + 0] + bv[2 * nt];
                float x1 = acc[mt][nt][half * 2 + 1] + bv[2 * nt + 1];
                if (ACT == 1) { x0 = silu(x0); x1 = silu(x1); }
                if (OUT_HALF) {
                    __half2* Ch = (__half2*)((__half*)Cv + (size_t)r * H_DIM + bn + col0 + c);
                    *Ch = __floats2half2_rn(x0, x1);
                } else {
                    float2 o; o.x = x0; o.y = x1;
                    *(float2*)((float*)Cv + (size_t)r * H_DIM + bn + col0 + c) = o;
                }
            }
        }
    }
}

// ---------------- weight transpose: W[K,512] fp32 -> Wt[512,K] fp16 ---------
__global__ void transpose_w16(const float* __restrict__ in, __half* __restrict__ out, int K)
{
    __shared__ float t[32][33];
    int k0 = blockIdx.x * 32, n0 = blockIdx.y * 32;
    int x = threadIdx.x, y = threadIdx.y;
    #pragma unroll
    for (int i = 0; i < 32; i += 8)
        t[y + i][x] = in[(size_t)(k0 + y + i) * 512 + n0 + x];
    __syncthreads();
    #pragma unroll
    for (int i = 0; i < 32; i += 8)
        out[(size_t)(n0 + y + i) * K + k0 + x] = __float2half_rn(t[x][y + i]);
}

// ---------------- fp32 -> fp16 bulk convert ---------------------------------
__global__ void f32_to_f16(const float* __restrict__ in, __half* __restrict__ out, size_t n)
{
    size_t i = ((size_t)blockIdx.x * blockDim.x + threadIdx.x) * 8;
    if (i >= n) return;
    float4 v0 = *(const float4*)(in + i);
    float4 v1 = *(const float4*)(in + i + 4);
    __half2 h[4];
    h[0] = __floats2half2_rn(v0.x, v0.y);
    h[1] = __floats2half2_rn(v0.z, v0.w);
    h[2] = __floats2half2_rn(v1.x, v1.y);
    h[3] = __floats2half2_rn(v1.z, v1.w);
    *(uint4*)(out + i) = *(uint4*)h;
}

// ---------------- LayerNorm (+residual) epilogues ---------------------------
__device__ __forceinline__ void row_stats(float v0, float v1, float& mean, float& rstd)
{
    float s = v0 + v1;
    float q = v0 * v0 + v1 * v1;
    #pragma unroll
    for (int o = 16; o > 0; o >>= 1) {
        s += __shfl_xor_sync(0xffffffffu, s, o);
        q += __shfl_xor_sync(0xffffffffu, q, o);
    }
    __shared__ float ss[8], sq[8];
    int w = threadIdx.x >> 5, l = threadIdx.x & 31;
    if (l == 0) { ss[w] = s; sq[w] = q; }
    __syncthreads();
    s = ss[0] + ss[1] + ss[2] + ss[3] + ss[4] + ss[5] + ss[6] + ss[7];
    q = sq[0] + sq[1] + sq[2] + sq[3] + sq[4] + sq[5] + sq[6] + sq[7];
    mean = s * (1.0f / 512.0f);
    float var = q * (1.0f / 512.0f) - mean * mean;
    rstd = rsqrtf(var + 1e-5f);
}

__global__ void ln_res_scatter(const float* __restrict__ y, const float* __restrict__ res,
                               const float* __restrict__ g, const float* __restrict__ b,
                               const int* __restrict__ dst, float* __restrict__ agg)
{
    const int row = blockIdx.x;
    const int t = threadIdx.x;
    const float* yr = y + (size_t)row * H_DIM;
    float v0 = yr[t], v1 = yr[t + 256];
    float mean, rstd;
    row_stats(v0, v1, mean, rstd);
    const float* rr = res + (size_t)row * H_DIM;
    float o0 = (v0 - mean) * rstd * g[t]       + b[t]       + rr[t];
    float o1 = (v1 - mean) * rstd * g[t + 256] + b[t + 256] + rr[t + 256];
    float* ag = agg + (size_t)dst[row] * H_DIM;
    atomicAdd(&ag[t],       o0);
    atomicAdd(&ag[t + 256], o1);
}

__global__ void ln_res_out(const float* __restrict__ y, const float* __restrict__ res,
                           const float* __restrict__ g, const float* __restrict__ b,
                           float* __restrict__ out)
{
    const int row = blockIdx.x;
    const int t = threadIdx.x;
    const float* yr = y + (size_t)row * H_DIM;
    float v0 = yr[t], v1 = yr[t + 256];
    float mean, rstd;
    row_stats(v0, v1, mean, rstd);
    const float* rr = res + (size_t)row * H_DIM;
    float* orow = out + (size_t)row * H_DIM;
    orow[t]       = (v0 - mean) * rstd * g[t]       + b[t]       + rr[t];
    orow[t + 256] = (v1 - mean) * rstd * g[t + 256] + b[t + 256] + rr[t + 256];
}

__global__ void zero_kernel(float* __restrict__ p, int n)
{
    int i = blockIdx.x * blockDim.x + threadIdx.x;
    if (i < n) p[i] = 0.0f;
}

// ---------------------------------------------------------------------------
extern "C" void kernel_launch(void* const* d_in, const int* in_sizes, int n_in,
                              void* d_out, int out_size)
{
    const float* grid_f = (const float*)d_in[0];
    const float* mesh_f = (const float*)d_in[1];
    const float* edge_f = (const float*)d_in[2];
    const int*   src    = (const int*)d_in[3];
    const int*   dst    = (const int*)d_in[4];
    const float* We1 = (const float*)d_in[5];  const float* be1 = (const float*)d_in[6];
    const float* We2 = (const float*)d_in[7];  const float* be2 = (const float*)d_in[8];
    const float* ge  = (const float*)d_in[9];  const float* bbe = (const float*)d_in[10];
    const float* Wn1 = (const float*)d_in[11]; const float* bn1 = (const float*)d_in[12];
    const float* Wn2 = (const float*)d_in[13]; const float* bn2 = (const float*)d_in[14];
    const float* gn  = (const float*)d_in[15]; const float* bbn = (const float*)d_in[16];
    const float* Wg1 = (const float*)d_in[17]; const float* bg1 = (const float*)d_in[18];
    const float* Wg2 = (const float*)d_in[19]; const float* bg2 = (const float*)d_in[20];
    const float* gg  = (const float*)d_in[21]; const float* bbg = (const float*)d_in[22];

    __half *e16, *g16, *m16, *agg16, *h16, *wt;
    float *y, *agg;
    cudaGetSymbolAddress((void**)&e16,   g_e16);
    cudaGetSymbolAddress((void**)&g16,   g_g16);
    cudaGetSymbolAddress((void**)&m16,   g_m16);
    cudaGetSymbolAddress((void**)&agg16, g_agg16);
    cudaGetSymbolAddress((void**)&h16,   g_h16);
    cudaGetSymbolAddress((void**)&y,     g_y);
    cudaGetSymbolAddress((void**)&agg,   g_agg);
    cudaGetSymbolAddress((void**)&wt,    g_wt16);

    cudaFuncSetAttribute(tc_gemm<0,0>, cudaFuncAttributeMaxDynamicSharedMemorySize, SMEM_BYTES);
    cudaFuncSetAttribute(tc_gemm<1,1>, cudaFuncAttributeMaxDynamicSharedMemorySize, SMEM_BYTES);

    float* grid_out = (float*)d_out;
    float* mesh_out = (float*)d_out + (size_t)NGRID * H_DIM;

    dim3 tb(32, 8);
    size_t ne = (size_t)NEDGE * H_DIM, ng = (size_t)NGRID * H_DIM, nm = (size_t)NMESH * H_DIM;

    // launches 0..4 (cheap), so launch #5 = edge GEMM1 lands under ncu (-s 5 -c 1)
    transpose_w16<<<dim3(48, 16), tb>>>(We1, wt + OFF_WE1T, 1536);                 // 0
    f32_to_f16<<<(unsigned)((ne / 8 + 255) / 256), 256>>>(edge_f, e16, ne);        // 1
    f32_to_f16<<<(unsigned)((ng / 8 + 255) / 256), 256>>>(grid_f, g16, ng);        // 2
    f32_to_f16<<<(unsigned)((nm / 8 + 255) / 256), 256>>>(mesh_f, m16, nm);        // 3
    { int n = NMESH * H_DIM; zero_kernel<<<(n + 255) / 256, 256>>>(agg, n); }      // 4

    // --- MeshEdgeBlock GEMM1 (launch 5: profiled)
    AViewH Ae = { e16, nullptr, g16, src, m16, dst };
    tc_gemm<1,1><<<dim3(2, NEDGE / 128), 256, SMEM_BYTES>>>(Ae, wt + OFF_WE1T, be1, h16, NEDGE, 1536);

    // remaining weight transposes
    transpose_w16<<<dim3(32, 16), tb>>>(Wn1, wt + OFF_WN1T, 1024);
    transpose_w16<<<dim3(16, 16), tb>>>(We2, wt + OFF_WE2T, 512);
    transpose_w16<<<dim3(16, 16), tb>>>(Wn2, wt + OFF_WN2T, 512);
    transpose_w16<<<dim3(16, 16), tb>>>(Wg1, wt + OFF_WG1T, 512);
    transpose_w16<<<dim3(16, 16), tb>>>(Wg2, wt + OFF_WG2T, 512);

    // --- MeshEdgeBlock GEMM2 + LN/scatter
    {
        AViewH Ah = { h16, nullptr, nullptr, nullptr, nullptr, nullptr };
        tc_gemm<0,0><<<dim3(2, NEDGE / 128), 256, SMEM_BYTES>>>(Ah, wt + OFF_WE2T, be2, y, NEDGE, 512);
        ln_res_scatter<<<NEDGE, 256>>>(y, edge_f, ge, bbe, dst, agg);
    }
    // --- MeshNodeBlock
    {
        f32_to_f16<<<(unsigned)((nm / 8 + 255) / 256), 256>>>(agg, agg16, nm);
        AViewH An = { m16, nullptr, agg16, nullptr, nullptr, nullptr };
        int gy = (NMESH + BM - 1) / BM;
        tc_gemm<1,1><<<dim3(2, gy), 256, SMEM_BYTES>>>(An, wt + OFF_WN1T, bn1, h16, NMESH, 1024);
        AViewH Ah = { h16, nullptr, nullptr, nullptr, nullptr, nullptr };
        tc_gemm<0,0><<<dim3(2, gy), 256, SMEM_BYTES>>>(Ah, wt + OFF_WN2T, bn2, y, NMESH, 512);
        ln_res_out<<<NMESH, 256>>>(y, mesh_f, gn, bbn, mesh_out);
    }
    // --- Grid node MLP
    {
        AViewH Ag = { g16, nullptr, nullptr, nullptr, nullptr, nullptr };
        tc_gemm<1,1><<<dim3(2, NGRID / 128), 256, SMEM_BYTES>>>(Ag, wt + OFF_WG1T, bg1, h16, NGRID, 512);
        AViewH Ah = { h16, nullptr, nullptr, nullptr, nullptr, nullptr };
        tc_gemm<0,0><<<dim3(2, NGRID / 128), 256, SMEM_BYTES>>>(Ah, wt + OFF_WG2T, bg2, y, NGRID, 512);
        ln_res_out<<<NGRID, 256>>>(y, grid_f, gg, bbg, grid_out);
    }
}

// round 10
// speedup vs baseline: 1.0773x; 1.0773x over previous
#include <cuda_runtime.h>
#include <cuda_fp16.h>
#include <math.h>
#include <stdint.h>

#define H_DIM  512
#define NGRID  65536
#define NMESH  10242
#define NEDGE  131072

// ---------------- scratch (device globals: allocation-guard safe) ----------
__device__ __half g_e16[(size_t)NEDGE * H_DIM];   // edge feats fp16
__device__ __half g_g16[(size_t)NGRID * H_DIM];   // grid feats fp16
__device__ __half g_m16[(size_t)NMESH * H_DIM];   // mesh feats fp16
__device__ __half g_agg16[(size_t)NMESH * H_DIM]; // agg fp16
__device__ __half g_h16[(size_t)NEDGE * H_DIM];   // hidden fp16 (edge/mesh path)
__device__ __half g_y16[(size_t)NEDGE * H_DIM];   // pre-LN fp16 (edge/mesh path)
__device__ __half g_hg16[(size_t)NGRID * H_DIM];  // hidden fp16 (grid path)
__device__ __half g_yg16[(size_t)NGRID * H_DIM];  // pre-LN fp16 (grid path)
__device__ float  g_agg[(size_t)NMESH * H_DIM];   // segment-sum fp32
__device__ __half g_wt16[(size_t)512 * 4608];     // transposed weights fp16 [N, K]

#define OFF_WE1T 0
#define OFF_WN1T (512*1536)
#define OFF_WE2T (OFF_WN1T + 512*1024)
#define OFF_WN2T (OFF_WE2T + 512*512)
#define OFF_WG1T (OFF_WN2T + 512*512)
#define OFF_WG2T (OFF_WG1T + 512*512)

// Virtual concatenated fp16 A matrix: segment s covers cols [s*512,(s+1)*512)
struct AViewH {
    const __half* base0; const int* idx0;
    const __half* base1; const int* idx1;
    const __half* base2; const int* idx2;
};

__device__ __forceinline__ const __half* seg_row_ptr(const AViewH& A, int seg, int r) {
    const __half* b; const int* ix;
    if (seg == 0)      { b = A.base0; ix = A.idx0; }
    else if (seg == 1) { b = A.base1; ix = A.idx1; }
    else               { b = A.base2; ix = A.idx2; }
    int ar = ix ? ix[r] : r;
    return b + (size_t)ar * H_DIM;
}

__device__ __forceinline__ float silu(float x) { return x / (1.0f + expf(-x)); }

__device__ __forceinline__ uint32_t smem_u32(const void* p) {
    uint32_t a;
    asm("{ .reg .u64 t; cvta.to.shared.u64 t, %1; cvt.u32.u64 %0, t; }" : "=r"(a) : "l"(p));
    return a;
}
__device__ __forceinline__ void cpasync16(uint32_t s, const void* g) {
    asm volatile("cp.async.cg.shared.global [%0], [%1], 16;" :: "r"(s), "l"(g));
}
__device__ __forceinline__ void mma_f16(float* d, const uint32_t* a, const uint32_t* b) {
    asm volatile(
        "mma.sync.aligned.m16n8k16.row.col.f32.f16.f16.f32 "
        "{%0,%1,%2,%3}, {%4,%5,%6,%7}, {%8,%9}, {%0,%1,%2,%3};"
        : "+f"(d[0]), "+f"(d[1]), "+f"(d[2]), "+f"(d[3])
        : "r"(a[0]), "r"(a[1]), "r"(a[2]), "r"(a[3]), "r"(b[0]), "r"(b[1]));
}

// ---------------- fp16 tensor-core GEMM: C = act(A @ Wt^T + bias) -----------
// BM=128, BN=256, BK=32(halfs). 512 threads = 16 warps (4m x 4n), warp 32x64.
// 4-stage cp.async pipeline (round-8 config: best measured).
#define BM 128
#define BN 256
#define SW  20
#define ATW (128 * SW)
#define BTW (256 * SW)
#define STW (ATW + BTW)
#define NSTG 4
#define SMEM_BYTES (NSTG * STW * 4)

template<int ACT>
__global__ __launch_bounds__(512)
void tc_gemm(AViewH A, const __half* __restrict__ Wt, const float* __restrict__ bias,
             __half* __restrict__ C, int M, int K)
{
    extern __shared__ uint32_t smw[];

    const int tid = threadIdx.x, wid = tid >> 5, lane = tid & 31;
    const int g = lane >> 2, tc = lane & 3;
    const int wm = wid & 3, wn = wid >> 2;               // 4 x 4 warp grid
    const int row0 = wm * 32, col0 = wn * 64;
    const int bm = blockIdx.y * BM, bn = blockIdx.x * BN;

    const int lr = tid >> 2;          // 0..127
    const int lc = tid & 3;           // chunk within row (8 halfs each)
    int arow = bm + lr; if (arow >= M) arow = M - 1;
    const __half* rpa[3];
    rpa[0] = seg_row_ptr(A, 0, arow);
    rpa[1] = (K > 512)  ? seg_row_ptr(A, 1, arow) : rpa[0];
    rpa[2] = (K > 1024) ? seg_row_ptr(A, 2, arow) : rpa[0];
    const __half* bp0 = Wt + (size_t)(bn + lr) * K;
    const __half* bp1 = Wt + (size_t)(bn + lr + 128) * K;

    const uint32_t sbase = smem_u32(smw);
    const uint32_t aOff  = ((uint32_t)(lr * SW + lc * 4)) * 4;
    const uint32_t bOff0 = ((uint32_t)(lr * SW + lc * 4)) * 4;
    const uint32_t bOff1 = ((uint32_t)((lr + 128) * SW + lc * 4)) * 4;

    auto load_tile = [&](int kt, int slot) {
        const int seg = kt >> 9, kin = kt & 511;
        const uint32_t sA = sbase + (uint32_t)(slot * STW) * 4;
        const uint32_t sB = sA + (uint32_t)ATW * 4;
        cpasync16(sA + aOff,  rpa[seg] + kin + lc * 8);
        cpasync16(sB + bOff0, bp0 + kt + lc * 8);
        cpasync16(sB + bOff1, bp1 + kt + lc * 8);
        asm volatile("cp.async.commit_group;");
    };

    float acc[2][8][4];
    #pragma unroll
    for (int i = 0; i < 2; i++)
        #pragma unroll
        for (int j = 0; j < 8; j++)
            #pragma unroll
            for (int e = 0; e < 4; e++) acc[i][j][e] = 0.0f;

    const int T = K >> 5;
    load_tile(0, 0);
    if (T > 1) load_tile(32, 1);
    if (T > 2) load_tile(64, 2);

    int slot = 0;
    for (int t = 0; t < T; ++t) {
        if      (t + 2 < T) asm volatile("cp.async.wait_group 2;");
        else if (t + 1 < T) asm volatile("cp.async.wait_group 1;");
        else                asm volatile("cp.async.wait_group 0;");
        __syncthreads();
        if (t + 3 < T) load_tile((t + 3) << 5, (slot + 3) & 3);

        const uint32_t* as = smw + slot * STW;
        const uint32_t* ws = as + ATW;
        #pragma unroll
        for (int kk = 0; kk < 2; kk++) {
            const int k0 = kk * 8;
            uint32_t af[2][4], bf[8][2];
            #pragma unroll
            for (int mt = 0; mt < 2; mt++) {
                const int r = row0 + mt * 16 + g;
                const int b0 = r * SW + k0 + tc;
                af[mt][0] = as[b0];
                af[mt][1] = as[b0 + 8 * SW];
                af[mt][2] = as[b0 + 4];
                af[mt][3] = as[b0 + 8 * SW + 4];
            }
            #pragma unroll
            for (int nt = 0; nt < 8; nt++) {
                const int n = col0 + nt * 8 + g;
                const int b0 = n * SW + k0 + tc;
                bf[nt][0] = ws[b0];
                bf[nt][1] = ws[b0 + 4];
            }
            #pragma unroll
            for (int mt = 0; mt < 2; mt++)
                #pragma unroll
                for (int nt = 0; nt < 8; nt++)
                    mma_f16(acc[mt][nt], af[mt], bf[nt]);
        }
        slot = (slot + 1) & 3;
    }

    // ---- epilogue: bias + optional SiLU, fp16 out
    float bv[16];
    #pragma unroll
    for (int nt = 0; nt < 8; nt++) {
        bv[2 * nt]     = bias[bn + col0 + nt * 8 + 2 * tc];
        bv[2 * nt + 1] = bias[bn + col0 + nt * 8 + 2 * tc + 1];
    }
    #pragma unroll
    for (int mt = 0; mt < 2; mt++) {
        const int r0 = bm + row0 + mt * 16 + g;
        #pragma unroll
        for (int half = 0; half < 2; half++) {
            const int r = r0 + half * 8;
            if (r >= M) continue;
            #pragma unroll
            for (int nt = 0; nt < 8; nt++) {
                const int c = nt * 8 + 2 * tc;
                float x0 = acc[mt][nt][half * 2 + 0] + bv[2 * nt];
                float x1 = acc[mt][nt][half * 2 + 1] + bv[2 * nt + 1];
                if (ACT == 1) { x0 = silu(x0); x1 = silu(x1); }
                *(__half2*)(C + (size_t)r * H_DIM + bn + col0 + c) = __floats2half2_rn(x0, x1);
            }
        }
    }
}

// ---------------- weight transpose: W[K,512] fp32 -> Wt[512,K] fp16 ---------
__global__ void transpose_w16(const float* __restrict__ in, __half* __restrict__ out, int K)
{
    __shared__ float t[32][33];
    int k0 = blockIdx.x * 32, n0 = blockIdx.y * 32;
    int x = threadIdx.x, y = threadIdx.y;
    #pragma unroll
    for (int i = 0; i < 32; i += 8)
        t[y + i][x] = in[(size_t)(k0 + y + i) * 512 + n0 + x];
    __syncthreads();
    #pragma unroll
    for (int i = 0; i < 32; i += 8)
        out[(size_t)(n0 + y + i) * K + k0 + x] = __float2half_rn(t[x][y + i]);
}

// ---------------- fp32 -> fp16 bulk convert ---------------------------------
__global__ void f32_to_f16(const float* __restrict__ in, __half* __restrict__ out, size_t n)
{
    size_t i = ((size_t)blockIdx.x * blockDim.x + threadIdx.x) * 8;
    if (i >= n) return;
    float4 v0 = *(const float4*)(in + i);
    float4 v1 = *(const float4*)(in + i + 4);
    __half2 h[4];
    h[0] = __floats2half2_rn(v0.x, v0.y);
    h[1] = __floats2half2_rn(v0.z, v0.w);
    h[2] = __floats2half2_rn(v1.x, v1.y);
    h[3] = __floats2half2_rn(v1.z, v1.w);
    *(uint4*)(out + i) = *(uint4*)h;
}

// ---------------- LayerNorm (+residual) epilogues (fp16 y input) ------------
__device__ __forceinline__ void row_stats(float v0, float v1, float& mean, float& rstd)
{
    float s = v0 + v1;
    float q = v0 * v0 + v1 * v1;
    #pragma unroll
    for (int o = 16; o > 0; o >>= 1) {
        s += __shfl_xor_sync(0xffffffffu, s, o);
        q += __shfl_xor_sync(0xffffffffu, q, o);
    }
    __shared__ float ss[8], sq[8];
    int w = threadIdx.x >> 5, l = threadIdx.x & 31;
    if (l == 0) { ss[w] = s; sq[w] = q; }
    __syncthreads();
    s = ss[0] + ss[1] + ss[2] + ss[3] + ss[4] + ss[5] + ss[6] + ss[7];
    q = sq[0] + sq[1] + sq[2] + sq[3] + sq[4] + sq[5] + sq[6] + sq[7];
    mean = s * (1.0f / 512.0f);
    float var = q * (1.0f / 512.0f) - mean * mean;
    rstd = rsqrtf(var + 1e-5f);
}

__global__ void ln_res_scatter(const __half* __restrict__ y, const float* __restrict__ res,
                               const float* __restrict__ g, const float* __restrict__ b,
                               const int* __restrict__ dst, float* __restrict__ agg)
{
    const int row = blockIdx.x;
    const int t = threadIdx.x;
    const __half* yr = y + (size_t)row * H_DIM;
    float v0 = __half2float(yr[t]), v1 = __half2float(yr[t + 256]);
    float mean, rstd;
    row_stats(v0, v1, mean, rstd);
    const float* rr = res + (size_t)row * H_DIM;
    float o0 = (v0 - mean) * rstd * g[t]       + b[t]       + rr[t];
    float o1 = (v1 - mean) * rstd * g[t + 256] + b[t + 256] + rr[t + 256];
    float* ag = agg + (size_t)dst[row] * H_DIM;
    atomicAdd(&ag[t],       o0);
    atomicAdd(&ag[t + 256], o1);
}

__global__ void ln_res_out(const __half* __restrict__ y, const float* __restrict__ res,
                           const float* __restrict__ g, const float* __restrict__ b,
                           float* __restrict__ out)
{
    const int row = blockIdx.x;
    const int t = threadIdx.x;
    const __half* yr = y + (size_t)row * H_DIM;
    float v0 = __half2float(yr[t]), v1 = __half2float(yr[t + 256]);
    float mean, rstd;
    row_stats(v0, v1, mean, rstd);
    const float* rr = res + (size_t)row * H_DIM;
    float* orow = out + (size_t)row * H_DIM;
    orow[t]       = (v0 - mean) * rstd * g[t]       + b[t]       + rr[t];
    orow[t + 256] = (v1 - mean) * rstd * g[t + 256] + b[t + 256] + rr[t + 256];
}

__global__ void zero_kernel(float* __restrict__ p, int n)
{
    int i = blockIdx.x * blockDim.x + threadIdx.x;
    if (i < n) p[i] = 0.0f;
}

// ---------------------------------------------------------------------------
extern "C" void kernel_launch(void* const* d_in, const int* in_sizes, int n_in,
                              void* d_out, int out_size)
{
    const float* grid_f = (const float*)d_in[0];
    const float* mesh_f = (const float*)d_in[1];
    const float* edge_f = (const float*)d_in[2];
    const int*   src    = (const int*)d_in[3];
    const int*   dst    = (const int*)d_in[4];
    const float* We1 = (const float*)d_in[5];  const float* be1 = (const float*)d_in[6];
    const float* We2 = (const float*)d_in[7];  const float* be2 = (const float*)d_in[8];
    const float* ge  = (const float*)d_in[9];  const float* bbe = (const float*)d_in[10];
    const float* Wn1 = (const float*)d_in[11]; const float* bn1 = (const float*)d_in[12];
    const float* Wn2 = (const float*)d_in[13]; const float* bn2 = (const float*)d_in[14];
    const float* gn  = (const float*)d_in[15]; const float* bbn = (const float*)d_in[16];
    const float* Wg1 = (const float*)d_in[17]; const float* bg1 = (const float*)d_in[18];
    const float* Wg2 = (const float*)d_in[19]; const float* bg2 = (const float*)d_in[20];
    const float* gg  = (const float*)d_in[21]; const float* bbg = (const float*)d_in[22];

    __half *e16, *g16, *m16, *agg16, *h16, *y16, *hg16, *yg16, *wt;
    float *agg;
    cudaGetSymbolAddress((void**)&e16,   g_e16);
    cudaGetSymbolAddress((void**)&g16,   g_g16);
    cudaGetSymbolAddress((void**)&m16,   g_m16);
    cudaGetSymbolAddress((void**)&agg16, g_agg16);
    cudaGetSymbolAddress((void**)&h16,   g_h16);
    cudaGetSymbolAddress((void**)&y16,   g_y16);
    cudaGetSymbolAddress((void**)&hg16,  g_hg16);
    cudaGetSymbolAddress((void**)&yg16,  g_yg16);
    cudaGetSymbolAddress((void**)&agg,   g_agg);
    cudaGetSymbolAddress((void**)&wt,    g_wt16);

    cudaFuncSetAttribute(tc_gemm<0>, cudaFuncAttributeMaxDynamicSharedMemorySize, SMEM_BYTES);
    cudaFuncSetAttribute(tc_gemm<1>, cudaFuncAttributeMaxDynamicSharedMemorySize, SMEM_BYTES);

    float* grid_out = (float*)d_out;
    float* mesh_out = (float*)d_out + (size_t)NGRID * H_DIM;

    dim3 tb(32, 8);
    size_t ne = (size_t)NEDGE * H_DIM, ng = (size_t)NGRID * H_DIM, nm = (size_t)NMESH * H_DIM;

    // ---- prologue (stream 0): all transposes + converts + zero
    transpose_w16<<<dim3(48, 16), tb>>>(We1, wt + OFF_WE1T, 1536);
    transpose_w16<<<dim3(32, 16), tb>>>(Wn1, wt + OFF_WN1T, 1024);
    transpose_w16<<<dim3(16, 16), tb>>>(We2, wt + OFF_WE2T, 512);
    transpose_w16<<<dim3(16, 16), tb>>>(Wn2, wt + OFF_WN2T, 512);
    transpose_w16<<<dim3(16, 16), tb>>>(Wg1, wt + OFF_WG1T, 512);
    transpose_w16<<<dim3(16, 16), tb>>>(Wg2, wt + OFF_WG2T, 512);
    f32_to_f16<<<(unsigned)((ne / 8 + 255) / 256), 256>>>(edge_f, e16, ne);
    f32_to_f16<<<(unsigned)((ng / 8 + 255) / 256), 256>>>(grid_f, g16, ng);
    f32_to_f16<<<(unsigned)((nm / 8 + 255) / 256), 256>>>(mesh_f, m16, nm);
    { int n = NMESH * H_DIM; zero_kernel<<<(n + 255) / 256, 256>>>(agg, n); }

    // ---- fork: grid-node path on a second stream (independent of edge/mesh)
    cudaStream_t s1;
    cudaStreamCreateWithFlags(&s1, cudaStreamNonBlocking);
    cudaEvent_t e0, e1;
    cudaEventCreateWithFlags(&e0, cudaEventDisableTiming);
    cudaEventCreateWithFlags(&e1, cudaEventDisableTiming);
    cudaEventRecord(e0, 0);
    cudaStreamWaitEvent(s1, e0, 0);
    {
        AViewH Ag = { g16, nullptr, nullptr, nullptr, nullptr, nullptr };
        tc_gemm<1><<<dim3(2, NGRID / 128), 512, SMEM_BYTES, s1>>>(Ag, wt + OFF_WG1T, bg1, hg16, NGRID, 512);
        AViewH Ah = { hg16, nullptr, nullptr, nullptr, nullptr, nullptr };
        tc_gemm<0><<<dim3(2, NGRID / 128), 512, SMEM_BYTES, s1>>>(Ah, wt + OFF_WG2T, bg2, yg16, NGRID, 512);
        ln_res_out<<<NGRID, 256, 0, s1>>>(yg16, grid_f, gg, bbg, grid_out);
    }
    cudaEventRecord(e1, s1);

    // ---- main (stream 0): edge block then mesh block
    {
        AViewH Ae = { e16, nullptr, g16, src, m16, dst };
        tc_gemm<1><<<dim3(2, NEDGE / 128), 512, SMEM_BYTES>>>(Ae, wt + OFF_WE1T, be1, h16, NEDGE, 1536);
        AViewH Ah = { h16, nullptr, nullptr, nullptr, nullptr, nullptr };
        tc_gemm<0><<<dim3(2, NEDGE / 128), 512, SMEM_BYTES>>>(Ah, wt + OFF_WE2T, be2, y16, NEDGE, 512);
        ln_res_scatter<<<NEDGE, 256>>>(y16, edge_f, ge, bbe, dst, agg);
    }
    {
        f32_to_f16<<<(unsigned)((nm / 8 + 255) / 256), 256>>>(agg, agg16, nm);
        AViewH An = { m16, nullptr, agg16, nullptr, nullptr, nullptr };
        int gy = (NMESH + BM - 1) / BM;
        tc_gemm<1><<<dim3(2, gy), 512, SMEM_BYTES>>>(An, wt + OFF_WN1T, bn1, h16, NMESH, 1024);
        AViewH Ah = { h16, nullptr, nullptr, nullptr, nullptr, nullptr };
        tc_gemm<0><<<dim3(2, gy), 512, SMEM_BYTES>>>(Ah, wt + OFF_WN2T, bn2, y16, NMESH, 512);
        ln_res_out<<<NMESH, 256>>>(y16, mesh_f, gn, bbn, mesh_out);
    }

    // ---- join grid path back into stream 0
    cudaStreamWaitEvent(0, e1, 0);
    cudaEventDestroy(e0);
    cudaEventDestroy(e1);
    cudaStreamDestroy(s1);
}

// round 11
// speedup vs baseline: 1.1950x; 1.1093x over previous
#include <cuda_runtime.h>
#include <cuda_fp16.h>
#include <math.h>
#include <stdint.h>

#define H_DIM  512
#define NGRID  65536
#define NMESH  10242
#define NEDGE  131072

// ---------------- scratch (device globals: allocation-guard safe) ----------
__device__ __half g_e16[(size_t)NEDGE * H_DIM];   // edge feats fp16
__device__ __half g_g16[(size_t)NGRID * H_DIM];   // grid feats fp16
__device__ __half g_m16[(size_t)NMESH * H_DIM];   // mesh feats fp16
__device__ __half g_agg16[(size_t)NMESH * H_DIM]; // agg fp16
__device__ __half g_h16[(size_t)NEDGE * H_DIM];   // hidden fp16 (edge/mesh path)
__device__ __half g_y16[(size_t)NEDGE * H_DIM];   // pre-LN fp16 (edge/mesh path)
__device__ __half g_hg16[(size_t)NGRID * H_DIM];  // hidden fp16 (grid path)
__device__ __half g_yg16[(size_t)NGRID * H_DIM];  // pre-LN fp16 (grid path)
__device__ float  g_pg[(size_t)NGRID * H_DIM];    // grid @ We1_g  (fp32 partial)
__device__ float  g_pm[(size_t)NMESH * H_DIM];    // mesh @ We1_m  (fp32 partial)
__device__ float  g_agg[(size_t)NMESH * H_DIM];   // segment-sum fp32
__device__ __half g_wt16[(size_t)512 * 4608];     // transposed weights fp16 [N, K]

#define OFF_WE1E 0
#define OFF_WE1G (512*512)
#define OFF_WE1M (2*512*512)
#define OFF_WN1  (3*512*512)
#define OFF_WE2  (OFF_WN1 + 512*1024)
#define OFF_WN2  (OFF_WE2 + 512*512)
#define OFF_WG1  (OFF_WN2 + 512*512)
#define OFF_WG2  (OFF_WG1 + 512*512)

// Virtual concatenated fp16 A matrix: segment s covers cols [s*512,(s+1)*512)
struct AViewH {
    const __half* base0; const int* idx0;
    const __half* base1; const int* idx1;
    const __half* base2; const int* idx2;
};

__device__ __forceinline__ const __half* seg_row_ptr(const AViewH& A, int seg, int r) {
    const __half* b; const int* ix;
    if (seg == 0)      { b = A.base0; ix = A.idx0; }
    else if (seg == 1) { b = A.base1; ix = A.idx1; }
    else               { b = A.base2; ix = A.idx2; }
    int ar = ix ? ix[r] : r;
    return b + (size_t)ar * H_DIM;
}

__device__ __forceinline__ float silu(float x) { return x / (1.0f + expf(-x)); }

__device__ __forceinline__ uint32_t smem_u32(const void* p) {
    uint32_t a;
    asm("{ .reg .u64 t; cvta.to.shared.u64 t, %1; cvt.u32.u64 %0, t; }" : "=r"(a) : "l"(p));
    return a;
}
__device__ __forceinline__ void cpasync16(uint32_t s, const void* g) {
    asm volatile("cp.async.cg.shared.global [%0], [%1], 16;" :: "r"(s), "l"(g));
}
__device__ __forceinline__ void mma_f16(float* d, const uint32_t* a, const uint32_t* b) {
    asm volatile(
        "mma.sync.aligned.m16n8k16.row.col.f32.f16.f16.f32 "
        "{%0,%1,%2,%3}, {%4,%5,%6,%7}, {%8,%9}, {%0,%1,%2,%3};"
        : "+f"(d[0]), "+f"(d[1]), "+f"(d[2]), "+f"(d[3])
        : "r"(a[0]), "r"(a[1]), "r"(a[2]), "r"(a[3]), "r"(b[0]), "r"(b[1]));
}

// ---------------- fp16 tensor-core GEMM ------------------------------------
// BM=128, BN=256, BK=32(halfs). 512 threads = 16 warps (4m x 4n), warp 32x64.
// EPI 0: bias+SiLU -> fp16      EPI 1: bias -> fp16
// EPI 2: no bias   -> fp32      EPI 3: bias + Pg[src]+Pm[dst] + SiLU -> fp16
#define BM 128
#define BN 256
#define SW  20
#define ATW (128 * SW)
#define BTW (256 * SW)
#define STW (ATW + BTW)
#define NSTG 4
#define SMEM_BYTES (NSTG * STW * 4)

template<int EPI>
__global__ __launch_bounds__(512)
void tc_gemm(AViewH A, const __half* __restrict__ Wt, const float* __restrict__ bias,
             void* __restrict__ Cv, int M, int K,
             const float* __restrict__ Pg, const float* __restrict__ Pm,
             const int* __restrict__ src, const int* __restrict__ dst)
{
    extern __shared__ uint32_t smw[];

    const int tid = threadIdx.x, wid = tid >> 5, lane = tid & 31;
    const int g = lane >> 2, tc = lane & 3;
    const int wm = wid & 3, wn = wid >> 2;               // 4 x 4 warp grid
    const int row0 = wm * 32, col0 = wn * 64;
    const int bm = blockIdx.y * BM, bn = blockIdx.x * BN;

    const int lr = tid >> 2;          // 0..127
    const int lc = tid & 3;           // chunk within row (8 halfs each)
    int arow = bm + lr; if (arow >= M) arow = M - 1;
    const __half* rpa[3];
    rpa[0] = seg_row_ptr(A, 0, arow);
    rpa[1] = (K > 512)  ? seg_row_ptr(A, 1, arow) : rpa[0];
    rpa[2] = (K > 1024) ? seg_row_ptr(A, 2, arow) : rpa[0];
    const __half* bp0 = Wt + (size_t)(bn + lr) * K;
    const __half* bp1 = Wt + (size_t)(bn + lr + 128) * K;

    const uint32_t sbase = smem_u32(smw);
    const uint32_t aOff  = ((uint32_t)(lr * SW + lc * 4)) * 4;
    const uint32_t bOff0 = ((uint32_t)(lr * SW + lc * 4)) * 4;
    const uint32_t bOff1 = ((uint32_t)((lr + 128) * SW + lc * 4)) * 4;

    auto load_tile = [&](int kt, int slot) {
        const int seg = kt >> 9, kin = kt & 511;
        const uint32_t sA = sbase + (uint32_t)(slot * STW) * 4;
        const uint32_t sB = sA + (uint32_t)ATW * 4;
        cpasync16(sA + aOff,  rpa[seg] + kin + lc * 8);
        cpasync16(sB + bOff0, bp0 + kt + lc * 8);
        cpasync16(sB + bOff1, bp1 + kt + lc * 8);
        asm volatile("cp.async.commit_group;");
    };

    float acc[2][8][4];
    #pragma unroll
    for (int i = 0; i < 2; i++)
        #pragma unroll
        for (int j = 0; j < 8; j++)
            #pragma unroll
            for (int e = 0; e < 4; e++) acc[i][j][e] = 0.0f;

    const int T = K >> 5;
    load_tile(0, 0);
    if (T > 1) load_tile(32, 1);
    if (T > 2) load_tile(64, 2);

    int slot = 0;
    for (int t = 0; t < T; ++t) {
        if      (t + 2 < T) asm volatile("cp.async.wait_group 2;");
        else if (t + 1 < T) asm volatile("cp.async.wait_group 1;");
        else                asm volatile("cp.async.wait_group 0;");
        __syncthreads();
        if (t + 3 < T) load_tile((t + 3) << 5, (slot + 3) & 3);

        const uint32_t* as = smw + slot * STW;
        const uint32_t* ws = as + ATW;
        #pragma unroll
        for (int kk = 0; kk < 2; kk++) {
            const int k0 = kk * 8;
            uint32_t af[2][4], bf[8][2];
            #pragma unroll
            for (int mt = 0; mt < 2; mt++) {
                const int r = row0 + mt * 16 + g;
                const int b0 = r * SW + k0 + tc;
                af[mt][0] = as[b0];
                af[mt][1] = as[b0 + 8 * SW];
                af[mt][2] = as[b0 + 4];
                af[mt][3] = as[b0 + 8 * SW + 4];
            }
            #pragma unroll
            for (int nt = 0; nt < 8; nt++) {
                const int n = col0 + nt * 8 + g;
                const int b0 = n * SW + k0 + tc;
                bf[nt][0] = ws[b0];
                bf[nt][1] = ws[b0 + 4];
            }
            #pragma unroll
            for (int mt = 0; mt < 2; mt++)
                #pragma unroll
                for (int nt = 0; nt < 8; nt++)
                    mma_f16(acc[mt][nt], af[mt], bf[nt]);
        }
        slot = (slot + 1) & 3;
    }

    // ---- epilogues ---------------------------------------------------------
    if (EPI == 2) {
        float* C = (float*)Cv;
        #pragma unroll
        for (int mt = 0; mt < 2; mt++) {
            #pragma unroll
            for (int half = 0; half < 2; half++) {
                const int r = bm + row0 + mt * 16 + g + half * 8;
                if (r >= M) continue;
                float* crow = C + (size_t)r * H_DIM + bn + col0;
                #pragma unroll
                for (int nt = 0; nt < 8; nt++) {
                    const int c = nt * 8 + 2 * tc;
                    float2 o;
                    o.x = acc[mt][nt][half * 2 + 0];
                    o.y = acc[mt][nt][half * 2 + 1];
                    *(float2*)(crow + c) = o;
                }
            }
        }
        return;
    }

    float bv[16];
    #pragma unroll
    for (int nt = 0; nt < 8; nt++) {
        bv[2 * nt]     = bias[bn + col0 + nt * 8 + 2 * tc];
        bv[2 * nt + 1] = bias[bn + col0 + nt * 8 + 2 * tc + 1];
    }
    __half* C = (__half*)Cv;
    #pragma unroll
    for (int mt = 0; mt < 2; mt++) {
        #pragma unroll
        for (int half = 0; half < 2; half++) {
            const int r = bm + row0 + mt * 16 + g + half * 8;
            if (r >= M) continue;
            const float* pgr = nullptr; const float* pmr = nullptr;
            if (EPI == 3) {
                pgr = Pg + (size_t)src[r] * H_DIM + bn + col0;
                pmr = Pm + (size_t)dst[r] * H_DIM + bn + col0;
            }
            #pragma unroll
            for (int nt = 0; nt < 8; nt++) {
                const int c = nt * 8 + 2 * tc;
                float x0 = acc[mt][nt][half * 2 + 0] + bv[2 * nt];
                float x1 = acc[mt][nt][half * 2 + 1] + bv[2 * nt + 1];
                if (EPI == 3) {
                    float2 pg2 = *(const float2*)(pgr + c);
                    float2 pm2 = *(const float2*)(pmr + c);
                    x0 += pg2.x + pm2.x;
                    x1 += pg2.y + pm2.y;
                }
                if (EPI == 0 || EPI == 3) { x0 = silu(x0); x1 = silu(x1); }
                *(__half2*)(C + (size_t)r * H_DIM + bn + col0 + c) = __floats2half2_rn(x0, x1);
            }
        }
    }
}

// ---------------- weight transpose: W[K,512] fp32 -> Wt[512,K] fp16 ---------
__global__ void transpose_w16(const float* __restrict__ in, __half* __restrict__ out, int K)
{
    __shared__ float t[32][33];
    int k0 = blockIdx.x * 32, n0 = blockIdx.y * 32;
    int x = threadIdx.x, y = threadIdx.y;
    #pragma unroll
    for (int i = 0; i < 32; i += 8)
        t[y + i][x] = in[(size_t)(k0 + y + i) * 512 + n0 + x];
    __syncthreads();
    #pragma unroll
    for (int i = 0; i < 32; i += 8)
        out[(size_t)(n0 + y + i) * K + k0 + x] = __float2half_rn(t[x][y + i]);
}

// ---------------- fp32 -> fp16 bulk convert ---------------------------------
__global__ void f32_to_f16(const float* __restrict__ in, __half* __restrict__ out, size_t n)
{
    size_t i = ((size_t)blockIdx.x * blockDim.x + threadIdx.x) * 8;
    if (i >= n) return;
    float4 v0 = *(const float4*)(in + i);
    float4 v1 = *(const float4*)(in + i + 4);
    __half2 h[4];
    h[0] = __floats2half2_rn(v0.x, v0.y);
    h[1] = __floats2half2_rn(v0.z, v0.w);
    h[2] = __floats2half2_rn(v1.x, v1.y);
    h[3] = __floats2half2_rn(v1.z, v1.w);
    *(uint4*)(out + i) = *(uint4*)h;
}

// ---------------- LayerNorm (+residual) epilogues (fp16 y input) ------------
__device__ __forceinline__ void row_stats(float v0, float v1, float& mean, float& rstd)
{
    float s = v0 + v1;
    float q = v0 * v0 + v1 * v1;
    #pragma unroll
    for (int o = 16; o > 0; o >>= 1) {
        s += __shfl_xor_sync(0xffffffffu, s, o);
        q += __shfl_xor_sync(0xffffffffu, q, o);
    }
    __shared__ float ss[8], sq[8];
    int w = threadIdx.x >> 5, l = threadIdx.x & 31;
    if (l == 0) { ss[w] = s; sq[w] = q; }
    __syncthreads();
    s = ss[0] + ss[1] + ss[2] + ss[3] + ss[4] + ss[5] + ss[6] + ss[7];
    q = sq[0] + sq[1] + sq[2] + sq[3] + sq[4] + sq[5] + sq[6] + sq[7];
    mean = s * (1.0f / 512.0f);
    float var = q * (1.0f / 512.0f) - mean * mean;
    rstd = rsqrtf(var + 1e-5f);
}

__global__ void ln_res_scatter(const __half* __restrict__ y, const float* __restrict__ res,
                               const float* __restrict__ g, const float* __restrict__ b,
                               const int* __restrict__ dst, float* __restrict__ agg)
{
    const int row = blockIdx.x;
    const int t = threadIdx.x;
    const __half* yr = y + (size_t)row * H_DIM;
    float v0 = __half2float(yr[t]), v1 = __half2float(yr[t + 256]);
    float mean, rstd;
    row_stats(v0, v1, mean, rstd);
    const float* rr = res + (size_t)row * H_DIM;
    float o0 = (v0 - mean) * rstd * g[t]       + b[t]       + rr[t];
    float o1 = (v1 - mean) * rstd * g[t + 256] + b[t + 256] + rr[t + 256];
    float* ag = agg + (size_t)dst[row] * H_DIM;
    atomicAdd(&ag[t],       o0);
    atomicAdd(&ag[t + 256], o1);
}

__global__ void ln_res_out(const __half* __restrict__ y, const float* __restrict__ res,
                           const float* __restrict__ g, const float* __restrict__ b,
                           float* __restrict__ out)
{
    const int row = blockIdx.x;
    const int t = threadIdx.x;
    const __half* yr = y + (size_t)row * H_DIM;
    float v0 = __half2float(yr[t]), v1 = __half2float(yr[t + 256]);
    float mean, rstd;
    row_stats(v0, v1, mean, rstd);
    const float* rr = res + (size_t)row * H_DIM;
    float* orow = out + (size_t)row * H_DIM;
    orow[t]       = (v0 - mean) * rstd * g[t]       + b[t]       + rr[t];
    orow[t + 256] = (v1 - mean) * rstd * g[t + 256] + b[t + 256] + rr[t + 256];
}

__global__ void zero_kernel(float* __restrict__ p, int n)
{
    int i = blockIdx.x * blockDim.x + threadIdx.x;
    if (i < n) p[i] = 0.0f;
}

// ---------------------------------------------------------------------------
extern "C" void kernel_launch(void* const* d_in, const int* in_sizes, int n_in,
                              void* d_out, int out_size)
{
    const float* grid_f = (const float*)d_in[0];
    const float* mesh_f = (const float*)d_in[1];
    const float* edge_f = (const float*)d_in[2];
    const int*   src    = (const int*)d_in[3];
    const int*   dst    = (const int*)d_in[4];
    const float* We1 = (const float*)d_in[5];  const float* be1 = (const float*)d_in[6];
    const float* We2 = (const float*)d_in[7];  const float* be2 = (const float*)d_in[8];
    const float* ge  = (const float*)d_in[9];  const float* bbe = (const float*)d_in[10];
    const float* Wn1 = (const float*)d_in[11]; const float* bn1 = (const float*)d_in[12];
    const float* Wn2 = (const float*)d_in[13]; const float* bn2 = (const float*)d_in[14];
    const float* gn  = (const float*)d_in[15]; const float* bbn = (const float*)d_in[16];
    const float* Wg1 = (const float*)d_in[17]; const float* bg1 = (const float*)d_in[18];
    const float* Wg2 = (const float*)d_in[19]; const float* bg2 = (const float*)d_in[20];
    const float* gg  = (const float*)d_in[21]; const float* bbg = (const float*)d_in[22];

    __half *e16, *g16, *m16, *agg16, *h16, *y16, *hg16, *yg16, *wt;
    float *agg, *pg, *pm;
    cudaGetSymbolAddress((void**)&e16,   g_e16);
    cudaGetSymbolAddress((void**)&g16,   g_g16);
    cudaGetSymbolAddress((void**)&m16,   g_m16);
    cudaGetSymbolAddress((void**)&agg16, g_agg16);
    cudaGetSymbolAddress((void**)&h16,   g_h16);
    cudaGetSymbolAddress((void**)&y16,   g_y16);
    cudaGetSymbolAddress((void**)&hg16,  g_hg16);
    cudaGetSymbolAddress((void**)&yg16,  g_yg16);
    cudaGetSymbolAddress((void**)&pg,    g_pg);
    cudaGetSymbolAddress((void**)&pm,    g_pm);
    cudaGetSymbolAddress((void**)&agg,   g_agg);
    cudaGetSymbolAddress((void**)&wt,    g_wt16);

    cudaFuncSetAttribute(tc_gemm<0>, cudaFuncAttributeMaxDynamicSharedMemorySize, SMEM_BYTES);
    cudaFuncSetAttribute(tc_gemm<1>, cudaFuncAttributeMaxDynamicSharedMemorySize, SMEM_BYTES);
    cudaFuncSetAttribute(tc_gemm<2>, cudaFuncAttributeMaxDynamicSharedMemorySize, SMEM_BYTES);
    cudaFuncSetAttribute(tc_gemm<3>, cudaFuncAttributeMaxDynamicSharedMemorySize, SMEM_BYTES);

    float* grid_out = (float*)d_out;
    float* mesh_out = (float*)d_out + (size_t)NGRID * H_DIM;

    dim3 tb(32, 8);
    size_t ne = (size_t)NEDGE * H_DIM, ng = (size_t)NGRID * H_DIM, nm = (size_t)NMESH * H_DIM;

    // ---- prologue (stream 0)
    transpose_w16<<<dim3(16, 16), tb>>>(We1,              wt + OFF_WE1E, 512);
    transpose_w16<<<dim3(16, 16), tb>>>(We1 + 512 * 512,  wt + OFF_WE1G, 512);
    transpose_w16<<<dim3(16, 16), tb>>>(We1 + 1024 * 512, wt + OFF_WE1M, 512);
    transpose_w16<<<dim3(32, 16), tb>>>(Wn1, wt + OFF_WN1, 1024);
    transpose_w16<<<dim3(16, 16), tb>>>(We2, wt + OFF_WE2, 512);
    transpose_w16<<<dim3(16, 16), tb>>>(Wn2, wt + OFF_WN2, 512);
    transpose_w16<<<dim3(16, 16), tb>>>(Wg1, wt + OFF_WG1, 512);
    transpose_w16<<<dim3(16, 16), tb>>>(Wg2, wt + OFF_WG2, 512);
    f32_to_f16<<<(unsigned)((ne / 8 + 255) / 256), 256>>>(edge_f, e16, ne);
    f32_to_f16<<<(unsigned)((ng / 8 + 255) / 256), 256>>>(grid_f, g16, ng);
    f32_to_f16<<<(unsigned)((nm / 8 + 255) / 256), 256>>>(mesh_f, m16, nm);
    { int n = NMESH * H_DIM; zero_kernel<<<(n + 255) / 256, 256>>>(agg, n); }

    // ---- fork: grid-node path on stream 1
    cudaStream_t s1;
    cudaStreamCreateWithFlags(&s1, cudaStreamNonBlocking);
    cudaEvent_t e0, e1;
    cudaEventCreateWithFlags(&e0, cudaEventDisableTiming);
    cudaEventCreateWithFlags(&e1, cudaEventDisableTiming);
    cudaEventRecord(e0, 0);
    cudaStreamWaitEvent(s1, e0, 0);
    {
        AViewH Ag = { g16, nullptr, nullptr, nullptr, nullptr, nullptr };
        tc_gemm<0><<<dim3(2, NGRID / 128), 512, SMEM_BYTES, s1>>>(
            Ag, wt + OFF_WG1, bg1, hg16, NGRID, 512, nullptr, nullptr, nullptr, nullptr);
        AViewH Ah = { hg16, nullptr, nullptr, nullptr, nullptr, nullptr };
        tc_gemm<1><<<dim3(2, NGRID / 128), 512, SMEM_BYTES, s1>>>(
            Ah, wt + OFF_WG2, bg2, yg16, NGRID, 512, nullptr, nullptr, nullptr, nullptr);
        ln_res_out<<<NGRID, 256, 0, s1>>>(yg16, grid_f, gg, bbg, grid_out);
    }
    cudaEventRecord(e1, s1);

    // ---- main (stream 0): factorized edge block, then mesh block
    {
        // partial products Pg = grid @ We1_g, Pm = mesh @ We1_m (fp32, no bias)
        AViewH Agp = { g16, nullptr, nullptr, nullptr, nullptr, nullptr };
        tc_gemm<2><<<dim3(2, NGRID / 128), 512, SMEM_BYTES>>>(
            Agp, wt + OFF_WE1G, nullptr, pg, NGRID, 512, nullptr, nullptr, nullptr, nullptr);
        AViewH Amp = { m16, nullptr, nullptr, nullptr, nullptr, nullptr };
        int gym = (NMESH + BM - 1) / BM;
        tc_gemm<2><<<dim3(2, gym), 512, SMEM_BYTES>>>(
            Amp, wt + OFF_WE1M, nullptr, pm, NMESH, 512, nullptr, nullptr, nullptr, nullptr);

        // edge GEMM1: e @ We1_e + Pg[src] + Pm[dst] + be1 -> SiLU -> h16
        AViewH Ae = { e16, nullptr, nullptr, nullptr, nullptr, nullptr };
        tc_gemm<3><<<dim3(2, NEDGE / 128), 512, SMEM_BYTES>>>(
            Ae, wt + OFF_WE1E, be1, h16, NEDGE, 512, pg, pm, src, dst);

        // edge GEMM2 + LN/residual/scatter
        AViewH Ah = { h16, nullptr, nullptr, nullptr, nullptr, nullptr };
        tc_gemm<1><<<dim3(2, NEDGE / 128), 512, SMEM_BYTES>>>(
            Ah, wt + OFF_WE2, be2, y16, NEDGE, 512, nullptr, nullptr, nullptr, nullptr);
        ln_res_scatter<<<NEDGE, 256>>>(y16, edge_f, ge, bbe, dst, agg);
    }
    {
        f32_to_f16<<<(unsigned)((nm / 8 + 255) / 256), 256>>>(agg, agg16, nm);
        AViewH An = { m16, nullptr, agg16, nullptr, nullptr, nullptr };
        int gy = (NMESH + BM - 1) / BM;
        tc_gemm<0><<<dim3(2, gy), 512, SMEM_BYTES>>>(
            An, wt + OFF_WN1, bn1, h16, NMESH, 1024, nullptr, nullptr, nullptr, nullptr);
        AViewH Ah = { h16, nullptr, nullptr, nullptr, nullptr, nullptr };
        tc_gemm<1><<<dim3(2, gy), 512, SMEM_BYTES>>>(
            Ah, wt + OFF_WN2, bn2, y16, NMESH, 512, nullptr, nullptr, nullptr, nullptr);
        ln_res_out<<<NMESH, 256>>>(y16, mesh_f, gn, bbn, mesh_out);
    }

    // ---- join
    cudaStreamWaitEvent(0, e1, 0);
    cudaEventDestroy(e0);
    cudaEventDestroy(e1);
    cudaStreamDestroy(s1);
}

// round 12
// speedup vs baseline: 1.2557x; 1.0507x over previous
#include <cuda_runtime.h>
#include <cuda_fp16.h>
#include <math.h>
#include <stdint.h>

#define H_DIM  512
#define NGRID  65536
#define NMESH  10242
#define NEDGE  131072

// ---------------- scratch (device globals: allocation-guard safe) ----------
__device__ __half g_e16[(size_t)NEDGE * H_DIM];
__device__ __half g_g16[(size_t)NGRID * H_DIM];
__device__ __half g_m16[(size_t)NMESH * H_DIM];
__device__ __half g_agg16[(size_t)NMESH * H_DIM];
__device__ __half g_h16[(size_t)NEDGE * H_DIM];
__device__ __half g_y16[(size_t)NEDGE * H_DIM];
__device__ __half g_hg16[(size_t)NGRID * H_DIM];
__device__ __half g_yg16[(size_t)NGRID * H_DIM];
__device__ __half g_pg16[(size_t)NGRID * H_DIM];  // grid @ We1_g (fp16)
__device__ __half g_pm16[(size_t)NMESH * H_DIM];  // mesh @ We1_m (fp16)
__device__ float  g_agg[(size_t)NMESH * H_DIM];
__device__ __half g_wt16[(size_t)512 * 4608];

// weight layout (fp16 elems)
#define OFF_CMB  0                        // [1024,512]: rows 0-511 Wg1^T, 512-1023 We1G^T
#define OFF_WE1E (1024*512)
#define OFF_WE1M (OFF_WE1E + 512*512)
#define OFF_WN1  (OFF_WE1M + 512*512)     // [512,1024]
#define OFF_WE2  (OFF_WN1 + 512*1024)
#define OFF_WN2  (OFF_WE2 + 512*512)
#define OFF_WG2  (OFF_WN2 + 512*512)

struct AViewH {
    const __half* base0; const int* idx0;
    const __half* base1; const int* idx1;
    const __half* base2; const int* idx2;
};

__device__ __forceinline__ const __half* seg_row_ptr(const AViewH& A, int seg, int r) {
    const __half* b; const int* ix;
    if (seg == 0)      { b = A.base0; ix = A.idx0; }
    else if (seg == 1) { b = A.base1; ix = A.idx1; }
    else               { b = A.base2; ix = A.idx2; }
    int ar = ix ? ix[r] : r;
    return b + (size_t)ar * H_DIM;
}

__device__ __forceinline__ float silu(float x) { return x / (1.0f + expf(-x)); }

__device__ __forceinline__ uint32_t smem_u32(const void* p) {
    uint32_t a;
    asm("{ .reg .u64 t; cvta.to.shared.u64 t, %1; cvt.u32.u64 %0, t; }" : "=r"(a) : "l"(p));
    return a;
}
__device__ __forceinline__ void cpasync16(uint32_t s, const void* g) {
    asm volatile("cp.async.cg.shared.global [%0], [%1], 16;" :: "r"(s), "l"(g));
}
__device__ __forceinline__ void mma_f16(float* d, const uint32_t* a, const uint32_t* b) {
    asm volatile(
        "mma.sync.aligned.m16n8k16.row.col.f32.f16.f16.f32 "
        "{%0,%1,%2,%3}, {%4,%5,%6,%7}, {%8,%9}, {%0,%1,%2,%3};"
        : "+f"(d[0]), "+f"(d[1]), "+f"(d[2]), "+f"(d[3])
        : "r"(a[0]), "r"(a[1]), "r"(a[2]), "r"(a[3]), "r"(b[0]), "r"(b[1]));
}

// ---------------- fp16 tensor-core GEMM ------------------------------------
// BM=128, BN=256, BK=32(halfs). 512 threads = 16 warps (4m x 4n), warp 32x64.
// EPI 0: bias+SiLU->fp16   EPI 1: bias->fp16   EPI 2: raw->fp16
// EPI 3: bias + Pg16[src]+Pm16[dst] + SiLU -> fp16
// EPI 4: split N=1024: cols<512 bias+SiLU->Cv, cols>=512 raw->C2
#define BM 128
#define BN 256
#define SW  20
#define ATW (128 * SW)
#define BTW (256 * SW)
#define STW (ATW + BTW)
#define NSTG 4
#define SMEM_BYTES (NSTG * STW * 4)

template<int EPI>
__global__ __launch_bounds__(512)
void tc_gemm(AViewH A, const __half* __restrict__ Wt, const float* __restrict__ bias,
             __half* __restrict__ Cv, __half* __restrict__ C2, int M, int K,
             const __half* __restrict__ Pg, const __half* __restrict__ Pm,
             const int* __restrict__ src, const int* __restrict__ dst)
{
    extern __shared__ uint32_t smw[];

    const int tid = threadIdx.x, wid = tid >> 5, lane = tid & 31;
    const int g = lane >> 2, tc = lane & 3;
    const int wm = wid & 3, wn = wid >> 2;
    const int row0 = wm * 32, col0 = wn * 64;
    const int bm = blockIdx.y * BM, bn = blockIdx.x * BN;

    const int lr = tid >> 2;
    const int lc = tid & 3;
    int arow = bm + lr; if (arow >= M) arow = M - 1;
    const __half* rpa[3];
    rpa[0] = seg_row_ptr(A, 0, arow);
    rpa[1] = (K > 512)  ? seg_row_ptr(A, 1, arow) : rpa[0];
    rpa[2] = (K > 1024) ? seg_row_ptr(A, 2, arow) : rpa[0];
    const __half* bp0 = Wt + (size_t)(bn + lr) * K;
    const __half* bp1 = Wt + (size_t)(bn + lr + 128) * K;

    const uint32_t sbase = smem_u32(smw);
    const uint32_t aOff  = ((uint32_t)(lr * SW + lc * 4)) * 4;
    const uint32_t bOff0 = ((uint32_t)(lr * SW + lc * 4)) * 4;
    const uint32_t bOff1 = ((uint32_t)((lr + 128) * SW + lc * 4)) * 4;

    auto load_tile = [&](int kt, int slot) {
        const int seg = kt >> 9, kin = kt & 511;
        const uint32_t sA = sbase + (uint32_t)(slot * STW) * 4;
        const uint32_t sB = sA + (uint32_t)ATW * 4;
        cpasync16(sA + aOff,  rpa[seg] + kin + lc * 8);
        cpasync16(sB + bOff0, bp0 + kt + lc * 8);
        cpasync16(sB + bOff1, bp1 + kt + lc * 8);
        asm volatile("cp.async.commit_group;");
    };

    float acc[2][8][4];
    #pragma unroll
    for (int i = 0; i < 2; i++)
        #pragma unroll
        for (int j = 0; j < 8; j++)
            #pragma unroll
            for (int e = 0; e < 4; e++) acc[i][j][e] = 0.0f;

    const int T = K >> 5;
    load_tile(0, 0);
    if (T > 1) load_tile(32, 1);
    if (T > 2) load_tile(64, 2);

    int slot = 0;
    for (int t = 0; t < T; ++t) {
        if      (t + 2 < T) asm volatile("cp.async.wait_group 2;");
        else if (t + 1 < T) asm volatile("cp.async.wait_group 1;");
        else                asm volatile("cp.async.wait_group 0;");
        __syncthreads();
        if (t + 3 < T) load_tile((t + 3) << 5, (slot + 3) & 3);

        const uint32_t* as = smw + slot * STW;
        const uint32_t* ws = as + ATW;
        #pragma unroll
        for (int kk = 0; kk < 2; kk++) {
            const int k0 = kk * 8;
            uint32_t af[2][4], bf[8][2];
            #pragma unroll
            for (int mt = 0; mt < 2; mt++) {
                const int r = row0 + mt * 16 + g;
                const int b0 = r * SW + k0 + tc;
                af[mt][0] = as[b0];
                af[mt][1] = as[b0 + 8 * SW];
                af[mt][2] = as[b0 + 4];
                af[mt][3] = as[b0 + 8 * SW + 4];
            }
            #pragma unroll
            for (int nt = 0; nt < 8; nt++) {
                const int n = col0 + nt * 8 + g;
                const int b0 = n * SW + k0 + tc;
                bf[nt][0] = ws[b0];
                bf[nt][1] = ws[b0 + 4];
            }
            #pragma unroll
            for (int mt = 0; mt < 2; mt++)
                #pragma unroll
                for (int nt = 0; nt < 8; nt++)
                    mma_f16(acc[mt][nt], af[mt], bf[nt]);
        }
        slot = (slot + 1) & 3;
    }

    // ---- epilogues ---------------------------------------------------------
    if (EPI == 2) {
        #pragma unroll
        for (int mt = 0; mt < 2; mt++)
            #pragma unroll
            for (int half = 0; half < 2; half++) {
                const int r = bm + row0 + mt * 16 + g + half * 8;
                if (r >= M) continue;
                #pragma unroll
                for (int nt = 0; nt < 8; nt++) {
                    const int c = nt * 8 + 2 * tc;
                    *(__half2*)(Cv + (size_t)r * H_DIM + bn + col0 + c) =
                        __floats2half2_rn(acc[mt][nt][half * 2], acc[mt][nt][half * 2 + 1]);
                }
            }
        return;
    }

    if (EPI == 4) {
        const bool fh = (bn < 512);
        __half* C = fh ? Cv : C2;
        const int cb = fh ? bn : bn - 512;
        float bv[16];
        #pragma unroll
        for (int nt = 0; nt < 8; nt++) {
            bv[2 * nt]     = fh ? bias[bn + col0 + nt * 8 + 2 * tc]     : 0.0f;
            bv[2 * nt + 1] = fh ? bias[bn + col0 + nt * 8 + 2 * tc + 1] : 0.0f;
        }
        #pragma unroll
        for (int mt = 0; mt < 2; mt++)
            #pragma unroll
            for (int half = 0; half < 2; half++) {
                const int r = bm + row0 + mt * 16 + g + half * 8;
                if (r >= M) continue;
                #pragma unroll
                for (int nt = 0; nt < 8; nt++) {
                    const int c = nt * 8 + 2 * tc;
                    float x0 = acc[mt][nt][half * 2 + 0] + bv[2 * nt];
                    float x1 = acc[mt][nt][half * 2 + 1] + bv[2 * nt + 1];
                    if (fh) { x0 = silu(x0); x1 = silu(x1); }
                    *(__half2*)(C + (size_t)r * H_DIM + cb + col0 + c) = __floats2half2_rn(x0, x1);
                }
            }
        return;
    }

    float bv[16];
    #pragma unroll
    for (int nt = 0; nt < 8; nt++) {
        bv[2 * nt]     = bias[bn + col0 + nt * 8 + 2 * tc];
        bv[2 * nt + 1] = bias[bn + col0 + nt * 8 + 2 * tc + 1];
    }
    #pragma unroll
    for (int mt = 0; mt < 2; mt++) {
        #pragma unroll
        for (int half = 0; half < 2; half++) {
            const int r = bm + row0 + mt * 16 + g + half * 8;
            if (r >= M) continue;
            const __half* pgr = nullptr; const __half* pmr = nullptr;
            if (EPI == 3) {
                pgr = Pg + (size_t)src[r] * H_DIM + bn + col0;
                pmr = Pm + (size_t)dst[r] * H_DIM + bn + col0;
            }
            #pragma unroll
            for (int nt = 0; nt < 8; nt++) {
                const int c = nt * 8 + 2 * tc;
                float x0 = acc[mt][nt][half * 2 + 0] + bv[2 * nt];
                float x1 = acc[mt][nt][half * 2 + 1] + bv[2 * nt + 1];
                if (EPI == 3) {
                    float2 pg2 = __half22float2(*(const __half2*)(pgr + c));
                    float2 pm2 = __half22float2(*(const __half2*)(pmr + c));
                    x0 += pg2.x + pm2.x;
                    x1 += pg2.y + pm2.y;
                }
                if (EPI == 0 || EPI == 3) { x0 = silu(x0); x1 = silu(x1); }
                *(__half2*)(Cv + (size_t)r * H_DIM + bn + col0 + c) = __floats2half2_rn(x0, x1);
            }
        }
    }
}

// ---------------- weight transpose: W[K,512] fp32 -> Wt[512,K] fp16 ---------
__global__ void transpose_w16(const float* __restrict__ in, __half* __restrict__ out, int K)
{
    __shared__ float t[32][33];
    int k0 = blockIdx.x * 32, n0 = blockIdx.y * 32;
    int x = threadIdx.x, y = threadIdx.y;
    #pragma unroll
    for (int i = 0; i < 32; i += 8)
        t[y + i][x] = in[(size_t)(k0 + y + i) * 512 + n0 + x];
    __syncthreads();
    #pragma unroll
    for (int i = 0; i < 32; i += 8)
        out[(size_t)(n0 + y + i) * K + k0 + x] = __float2half_rn(t[x][y + i]);
}

__global__ void f32_to_f16(const float* __restrict__ in, __half* __restrict__ out, size_t n)
{
    size_t i = ((size_t)blockIdx.x * blockDim.x + threadIdx.x) * 8;
    if (i >= n) return;
    float4 v0 = *(const float4*)(in + i);
    float4 v1 = *(const float4*)(in + i + 4);
    __half2 h[4];
    h[0] = __floats2half2_rn(v0.x, v0.y);
    h[1] = __floats2half2_rn(v0.z, v0.w);
    h[2] = __floats2half2_rn(v1.x, v1.y);
    h[3] = __floats2half2_rn(v1.z, v1.w);
    *(uint4*)(out + i) = *(uint4*)h;
}

// ---------------- LayerNorm (+residual) epilogues (fp16 y, vectorized) ------
__device__ __forceinline__ void row_stats(float v0, float v1, float& mean, float& rstd)
{
    float s = v0 + v1;
    float q = v0 * v0 + v1 * v1;
    #pragma unroll
    for (int o = 16; o > 0; o >>= 1) {
        s += __shfl_xor_sync(0xffffffffu, s, o);
        q += __shfl_xor_sync(0xffffffffu, q, o);
    }
    __shared__ float ss[8], sq[8];
    int w = threadIdx.x >> 5, l = threadIdx.x & 31;
    if (l == 0) { ss[w] = s; sq[w] = q; }
    __syncthreads();
    s = ss[0] + ss[1] + ss[2] + ss[3] + ss[4] + ss[5] + ss[6] + ss[7];
    q = sq[0] + sq[1] + sq[2] + sq[3] + sq[4] + sq[5] + sq[6] + sq[7];
    mean = s * (1.0f / 512.0f);
    float var = q * (1.0f / 512.0f) - mean * mean;
    rstd = rsqrtf(var + 1e-5f);
}

__global__ void ln_res_scatter(const __half* __restrict__ y, const float* __restrict__ res,
                               const float* __restrict__ g, const float* __restrict__ b,
                               const int* __restrict__ dst, float* __restrict__ agg)
{
    const int row = blockIdx.x;
    const int t = threadIdx.x;
    float2 v = __half22float2(((const __half2*)(y + (size_t)row * H_DIM))[t]);
    float mean, rstd;
    row_stats(v.x, v.y, mean, rstd);
    float2 rr = *(const float2*)(res + (size_t)row * H_DIM + 2 * t);
    float2 gg2 = *(const float2*)(g + 2 * t);
    float2 bb2 = *(const float2*)(b + 2 * t);
    float o0 = (v.x - mean) * rstd * gg2.x + bb2.x + rr.x;
    float o1 = (v.y - mean) * rstd * gg2.y + bb2.y + rr.y;
    float* ag = agg + (size_t)dst[row] * H_DIM + 2 * t;
    atomicAdd(ag,     o0);
    atomicAdd(ag + 1, o1);
}

__global__ void ln_res_out(const __half* __restrict__ y, const float* __restrict__ res,
                           const float* __restrict__ g, const float* __restrict__ b,
                           float* __restrict__ out)
{
    const int row = blockIdx.x;
    const int t = threadIdx.x;
    float2 v = __half22float2(((const __half2*)(y + (size_t)row * H_DIM))[t]);
    float mean, rstd;
    row_stats(v.x, v.y, mean, rstd);
    float2 rr = *(const float2*)(res + (size_t)row * H_DIM + 2 * t);
    float2 gg2 = *(const float2*)(g + 2 * t);
    float2 bb2 = *(const float2*)(b + 2 * t);
    float2 o;
    o.x = (v.x - mean) * rstd * gg2.x + bb2.x + rr.x;
    o.y = (v.y - mean) * rstd * gg2.y + bb2.y + rr.y;
    *(float2*)(out + (size_t)row * H_DIM + 2 * t) = o;
}

__global__ void zero_kernel(float* __restrict__ p, int n)
{
    int i = blockIdx.x * blockDim.x + threadIdx.x;
    if (i < n) p[i] = 0.0f;
}

// ---------------------------------------------------------------------------
extern "C" void kernel_launch(void* const* d_in, const int* in_sizes, int n_in,
                              void* d_out, int out_size)
{
    const float* grid_f = (const float*)d_in[0];
    const float* mesh_f = (const float*)d_in[1];
    const float* edge_f = (const float*)d_in[2];
    const int*   src    = (const int*)d_in[3];
    const int*   dst    = (const int*)d_in[4];
    const float* We1 = (const float*)d_in[5];  const float* be1 = (const float*)d_in[6];
    const float* We2 = (const float*)d_in[7];  const float* be2 = (const float*)d_in[8];
    const float* ge  = (const float*)d_in[9];  const float* bbe = (const float*)d_in[10];
    const float* Wn1 = (const float*)d_in[11]; const float* bn1 = (const float*)d_in[12];
    const float* Wn2 = (const float*)d_in[13]; const float* bn2 = (const float*)d_in[14];
    const float* gn  = (const float*)d_in[15]; const float* bbn = (const float*)d_in[16];
    const float* Wg1 = (const float*)d_in[17]; const float* bg1 = (const float*)d_in[18];
    const float* Wg2 = (const float*)d_in[19]; const float* bg2 = (const float*)d_in[20];
    const float* gg  = (const float*)d_in[21]; const float* bbg = (const float*)d_in[22];

    __half *e16, *g16, *m16, *agg16, *h16, *y16, *hg16, *yg16, *pg16, *pm16, *wt;
    float *agg;
    cudaGetSymbolAddress((void**)&e16,   g_e16);
    cudaGetSymbolAddress((void**)&g16,   g_g16);
    cudaGetSymbolAddress((void**)&m16,   g_m16);
    cudaGetSymbolAddress((void**)&agg16, g_agg16);
    cudaGetSymbolAddress((void**)&h16,   g_h16);
    cudaGetSymbolAddress((void**)&y16,   g_y16);
    cudaGetSymbolAddress((void**)&hg16,  g_hg16);
    cudaGetSymbolAddress((void**)&yg16,  g_yg16);
    cudaGetSymbolAddress((void**)&pg16,  g_pg16);
    cudaGetSymbolAddress((void**)&pm16,  g_pm16);
    cudaGetSymbolAddress((void**)&agg,   g_agg);
    cudaGetSymbolAddress((void**)&wt,    g_wt16);

    cudaFuncSetAttribute(tc_gemm<0>, cudaFuncAttributeMaxDynamicSharedMemorySize, SMEM_BYTES);
    cudaFuncSetAttribute(tc_gemm<1>, cudaFuncAttributeMaxDynamicSharedMemorySize, SMEM_BYTES);
    cudaFuncSetAttribute(tc_gemm<2>, cudaFuncAttributeMaxDynamicSharedMemorySize, SMEM_BYTES);
    cudaFuncSetAttribute(tc_gemm<3>, cudaFuncAttributeMaxDynamicSharedMemorySize, SMEM_BYTES);
    cudaFuncSetAttribute(tc_gemm<4>, cudaFuncAttributeMaxDynamicSharedMemorySize, SMEM_BYTES);

    float* grid_out = (float*)d_out;
    float* mesh_out = (float*)d_out + (size_t)NGRID * H_DIM;

    dim3 tb(32, 8);
    size_t ne = (size_t)NEDGE * H_DIM, ng = (size_t)NGRID * H_DIM, nm = (size_t)NMESH * H_DIM;

    // ---- fork s1 immediately; it owns the non-critical prologue
    cudaStream_t s1;
    cudaStreamCreateWithFlags(&s1, cudaStreamNonBlocking);
    cudaEvent_t evFork, evPro, evFus, evEnd;
    cudaEventCreateWithFlags(&evFork, cudaEventDisableTiming);
    cudaEventCreateWithFlags(&evPro,  cudaEventDisableTiming);
    cudaEventCreateWithFlags(&evFus,  cudaEventDisableTiming);
    cudaEventCreateWithFlags(&evEnd,  cudaEventDisableTiming);
    cudaEventRecord(evFork, 0);
    cudaStreamWaitEvent(s1, evFork, 0);

    // s1 prologue: everything NOT needed by stream-0's first GEMM
    transpose_w16<<<dim3(16, 16), tb, 0, s1>>>(We1,               wt + OFF_WE1E, 512);
    transpose_w16<<<dim3(16, 16), tb, 0, s1>>>(We1 + 1024 * 512,  wt + OFF_WE1M, 512);
    transpose_w16<<<dim3(32, 16), tb, 0, s1>>>(Wn1, wt + OFF_WN1, 1024);
    transpose_w16<<<dim3(16, 16), tb, 0, s1>>>(We2, wt + OFF_WE2, 512);
    transpose_w16<<<dim3(16, 16), tb, 0, s1>>>(Wn2, wt + OFF_WN2, 512);
    transpose_w16<<<dim3(16, 16), tb, 0, s1>>>(Wg2, wt + OFF_WG2, 512);
    f32_to_f16<<<(unsigned)((ne / 8 + 255) / 256), 256, 0, s1>>>(edge_f, e16, ne);
    f32_to_f16<<<(unsigned)((nm / 8 + 255) / 256), 256, 0, s1>>>(mesh_f, m16, nm);
    { int n = NMESH * H_DIM; zero_kernel<<<(n + 255) / 256, 256, 0, s1>>>(agg, n); }
    cudaEventRecord(evPro, s1);

    // stream 0 minimal prologue: combined [Wg1^T ; We1G^T] + g16 convert
    transpose_w16<<<dim3(16, 16), tb>>>(Wg1,             wt + OFF_CMB, 512);
    transpose_w16<<<dim3(16, 16), tb>>>(We1 + 512 * 512, wt + OFF_CMB + 512 * 512, 512);
    f32_to_f16<<<(unsigned)((ng / 8 + 255) / 256), 256>>>(grid_f, g16, ng);

    // fused grid-GEMM1 + Pg: g16 @ [Wg1; We1G]  -> hg16 (SiLU) | pg16 (raw)
    AViewH Ag = { g16, nullptr, nullptr, nullptr, nullptr, nullptr };
    tc_gemm<4><<<dim3(4, NGRID / 128), 512, SMEM_BYTES>>>(
        Ag, wt + OFF_CMB, bg1, hg16, pg16, NGRID, 512, nullptr, nullptr, nullptr, nullptr);
    cudaEventRecord(evFus, 0);

    // s1 tail: grid GEMM2 + LN (needs hg16 + Wg2)
    cudaStreamWaitEvent(s1, evFus, 0);
    {
        AViewH Ah = { hg16, nullptr, nullptr, nullptr, nullptr, nullptr };
        tc_gemm<1><<<dim3(2, NGRID / 128), 512, SMEM_BYTES, s1>>>(
            Ah, wt + OFF_WG2, bg2, yg16, nullptr, NGRID, 512, nullptr, nullptr, nullptr, nullptr);
        ln_res_out<<<NGRID, 256, 0, s1>>>(yg16, grid_f, gg, bbg, grid_out);
    }
    cudaEventRecord(evEnd, s1);

    // stream 0: wait for s1 prologue, then edge + mesh blocks
    cudaStreamWaitEvent(0, evPro, 0);
    {
        // Pm = mesh @ We1_m (fp16 raw)
        AViewH Amp = { m16, nullptr, nullptr, nullptr, nullptr, nullptr };
        int gym = (NMESH + BM - 1) / BM;
        tc_gemm<2><<<dim3(2, gym), 512, SMEM_BYTES>>>(
            Amp, wt + OFF_WE1M, nullptr, pm16, nullptr, NMESH, 512, nullptr, nullptr, nullptr, nullptr);

        // edge GEMM1: e @ We1_e + Pg16[src] + Pm16[dst] + be1 -> SiLU -> h16
        AViewH Ae = { e16, nullptr, nullptr, nullptr, nullptr, nullptr };
        tc_gemm<3><<<dim3(2, NEDGE / 128), 512, SMEM_BYTES>>>(
            Ae, wt + OFF_WE1E, be1, h16, nullptr, NEDGE, 512, pg16, pm16, src, dst);

        // edge GEMM2 + LN/residual/scatter
        AViewH Ah = { h16, nullptr, nullptr, nullptr, nullptr, nullptr };
        tc_gemm<1><<<dim3(2, NEDGE / 128), 512, SMEM_BYTES>>>(
            Ah, wt + OFF_WE2, be2, y16, nullptr, NEDGE, 512, nullptr, nullptr, nullptr, nullptr);
        ln_res_scatter<<<NEDGE, 256>>>(y16, edge_f, ge, bbe, dst, agg);
    }
    {
        f32_to_f16<<<(unsigned)((nm / 8 + 255) / 256), 256>>>(agg, agg16, nm);
        AViewH An = { m16, nullptr, agg16, nullptr, nullptr, nullptr };
        int gy = (NMESH + BM - 1) / BM;
        tc_gemm<0><<<dim3(2, gy), 512, SMEM_BYTES>>>(
            An, wt + OFF_WN1, bn1, h16, nullptr, NMESH, 1024, nullptr, nullptr, nullptr, nullptr);
        AViewH Ah = { h16, nullptr, nullptr, nullptr, nullptr, nullptr };
        tc_gemm<1><<<dim3(2, gy), 512, SMEM_BYTES>>>(
            Ah, wt + OFF_WN2, bn2, y16, nullptr, NMESH, 512, nullptr, nullptr, nullptr, nullptr);
        ln_res_out<<<NMESH, 256>>>(y16, mesh_f, gn, bbn, mesh_out);
    }

    // ---- join
    cudaStreamWaitEvent(0, evEnd, 0);
    cudaEventDestroy(evFork);
    cudaEventDestroy(evPro);
    cudaEventDestroy(evFus);
    cudaEventDestroy(evEnd);
    cudaStreamDestroy(s1);
}

// round 13
// speedup vs baseline: 1.2723x; 1.0133x over previous
#include <cuda_runtime.h>
#include <cuda_fp16.h>
#include <math.h>
#include <stdint.h>

#define H_DIM  512
#define NGRID  65536
#define NMESH  10242
#define NEDGE  131072

// ---------------- scratch (device globals: allocation-guard safe) ----------
__device__ __half g_e16[(size_t)NEDGE * H_DIM];
__device__ __half g_g16[(size_t)NGRID * H_DIM];
__device__ __half g_m16[(size_t)NMESH * H_DIM];
__device__ __half g_agg16[(size_t)NMESH * H_DIM];
__device__ __half g_h16[(size_t)NEDGE * H_DIM];
__device__ __half g_y16[(size_t)NEDGE * H_DIM];
__device__ __half g_hg16[(size_t)NGRID * H_DIM];
__device__ __half g_yg16[(size_t)NGRID * H_DIM];
__device__ __half g_pg16[(size_t)NGRID * H_DIM];  // grid @ We1_g (fp16)
__device__ __half g_pm16[(size_t)NMESH * H_DIM];  // mesh @ We1_m (fp16)
__device__ float  g_agg[(size_t)NMESH * H_DIM];
__device__ __half g_wt16[(size_t)512 * 4608];

// weight layout (fp16 elems)
#define OFF_CMB  0                        // [1024,512]: rows 0-511 Wg1^T, 512-1023 We1G^T
#define OFF_WE1E (1024*512)
#define OFF_WE1M (OFF_WE1E + 512*512)
#define OFF_WN1  (OFF_WE1M + 512*512)     // [512,1024]
#define OFF_WE2  (OFF_WN1 + 512*1024)
#define OFF_WN2  (OFF_WE2 + 512*512)
#define OFF_WG2  (OFF_WN2 + 512*512)

struct AViewH {
    const __half* base0; const int* idx0;
    const __half* base1; const int* idx1;
    const __half* base2; const int* idx2;
};

__device__ __forceinline__ const __half* seg_row_ptr(const AViewH& A, int seg, int r) {
    const __half* b; const int* ix;
    if (seg == 0)      { b = A.base0; ix = A.idx0; }
    else if (seg == 1) { b = A.base1; ix = A.idx1; }
    else               { b = A.base2; ix = A.idx2; }
    int ar = ix ? ix[r] : r;
    return b + (size_t)ar * H_DIM;
}

__device__ __forceinline__ float silu(float x) { return x / (1.0f + expf(-x)); }

__device__ __forceinline__ uint32_t smem_u32(const void* p) {
    uint32_t a;
    asm("{ .reg .u64 t; cvta.to.shared.u64 t, %1; cvt.u32.u64 %0, t; }" : "=r"(a) : "l"(p));
    return a;
}
__device__ __forceinline__ void cpasync16(uint32_t s, const void* g) {
    asm volatile("cp.async.cg.shared.global [%0], [%1], 16;" :: "r"(s), "l"(g));
}
__device__ __forceinline__ void mma_f16(float* d, const uint32_t* a, const uint32_t* b) {
    asm volatile(
        "mma.sync.aligned.m16n8k16.row.col.f32.f16.f16.f32 "
        "{%0,%1,%2,%3}, {%4,%5,%6,%7}, {%8,%9}, {%0,%1,%2,%3};"
        : "+f"(d[0]), "+f"(d[1]), "+f"(d[2]), "+f"(d[3])
        : "r"(a[0]), "r"(a[1]), "r"(a[2]), "r"(a[3]), "r"(b[0]), "r"(b[1]));
}

// ---------------- fp16 tensor-core GEMM ------------------------------------
// BM=128, BN=256, BK=32(halfs). 512 threads = 16 warps (4m x 4n), warp 32x64.
// EPI 0: bias+SiLU->fp16   EPI 1: bias->fp16   EPI 2: raw->fp16
// EPI 3: bias + Pg16[src]+Pm16[dst] + SiLU -> fp16
// EPI 4: split N=1024: cols<512 bias+SiLU->Cv, cols>=512 raw->C2
#define BM 128
#define BN 256
#define SW  20
#define ATW (128 * SW)
#define BTW (256 * SW)
#define STW (ATW + BTW)
#define NSTG 4
#define SMEM_BYTES (NSTG * STW * 4)

template<int EPI>
__global__ __launch_bounds__(512)
void tc_gemm(AViewH A, const __half* __restrict__ Wt, const float* __restrict__ bias,
             __half* __restrict__ Cv, __half* __restrict__ C2, int M, int K,
             const __half* __restrict__ Pg, const __half* __restrict__ Pm,
             const int* __restrict__ src, const int* __restrict__ dst)
{
    extern __shared__ uint32_t smw[];

    const int tid = threadIdx.x, wid = tid >> 5, lane = tid & 31;
    const int g = lane >> 2, tc = lane & 3;
    const int wm = wid & 3, wn = wid >> 2;
    const int row0 = wm * 32, col0 = wn * 64;
    const int bm = blockIdx.y * BM, bn = blockIdx.x * BN;

    const int lr = tid >> 2;
    const int lc = tid & 3;
    int arow = bm + lr; if (arow >= M) arow = M - 1;
    const __half* rpa[3];
    rpa[0] = seg_row_ptr(A, 0, arow);
    rpa[1] = (K > 512)  ? seg_row_ptr(A, 1, arow) : rpa[0];
    rpa[2] = (K > 1024) ? seg_row_ptr(A, 2, arow) : rpa[0];
    const __half* bp0 = Wt + (size_t)(bn + lr) * K;
    const __half* bp1 = Wt + (size_t)(bn + lr + 128) * K;

    const uint32_t sbase = smem_u32(smw);
    const uint32_t aOff  = ((uint32_t)(lr * SW + lc * 4)) * 4;
    const uint32_t bOff0 = ((uint32_t)(lr * SW + lc * 4)) * 4;
    const uint32_t bOff1 = ((uint32_t)((lr + 128) * SW + lc * 4)) * 4;

    auto load_tile = [&](int kt, int slot) {
        const int seg = kt >> 9, kin = kt & 511;
        const uint32_t sA = sbase + (uint32_t)(slot * STW) * 4;
        const uint32_t sB = sA + (uint32_t)ATW * 4;
        cpasync16(sA + aOff,  rpa[seg] + kin + lc * 8);
        cpasync16(sB + bOff0, bp0 + kt + lc * 8);
        cpasync16(sB + bOff1, bp1 + kt + lc * 8);
        asm volatile("cp.async.commit_group;");
    };

    float acc[2][8][4];
    #pragma unroll
    for (int i = 0; i < 2; i++)
        #pragma unroll
        for (int j = 0; j < 8; j++)
            #pragma unroll
            for (int e = 0; e < 4; e++) acc[i][j][e] = 0.0f;

    const int T = K >> 5;
    load_tile(0, 0);
    if (T > 1) load_tile(32, 1);
    if (T > 2) load_tile(64, 2);

    int slot = 0;
    for (int t = 0; t < T; ++t) {
        if      (t + 2 < T) asm volatile("cp.async.wait_group 2;");
        else if (t + 1 < T) asm volatile("cp.async.wait_group 1;");
        else                asm volatile("cp.async.wait_group 0;");
        __syncthreads();
        if (t + 3 < T) load_tile((t + 3) << 5, (slot + 3) & 3);

        const uint32_t* as = smw + slot * STW;
        const uint32_t* ws = as + ATW;
        #pragma unroll
        for (int kk = 0; kk < 2; kk++) {
            const int k0 = kk * 8;
            uint32_t af[2][4], bf[8][2];
            #pragma unroll
            for (int mt = 0; mt < 2; mt++) {
                const int r = row0 + mt * 16 + g;
                const int b0 = r * SW + k0 + tc;
                af[mt][0] = as[b0];
                af[mt][1] = as[b0 + 8 * SW];
                af[mt][2] = as[b0 + 4];
                af[mt][3] = as[b0 + 8 * SW + 4];
            }
            #pragma unroll
            for (int nt = 0; nt < 8; nt++) {
                const int n = col0 + nt * 8 + g;
                const int b0 = n * SW + k0 + tc;
                bf[nt][0] = ws[b0];
                bf[nt][1] = ws[b0 + 4];
            }
            #pragma unroll
            for (int mt = 0; mt < 2; mt++)
                #pragma unroll
                for (int nt = 0; nt < 8; nt++)
                    mma_f16(acc[mt][nt], af[mt], bf[nt]);
        }
        slot = (slot + 1) & 3;
    }

    // ---- epilogues ---------------------------------------------------------
    if (EPI == 2) {
        #pragma unroll
        for (int mt = 0; mt < 2; mt++)
            #pragma unroll
            for (int half = 0; half < 2; half++) {
                const int r = bm + row0 + mt * 16 + g + half * 8;
                if (r >= M) continue;
                #pragma unroll
                for (int nt = 0; nt < 8; nt++) {
                    const int c = nt * 8 + 2 * tc;
                    *(__half2*)(Cv + (size_t)r * H_DIM + bn + col0 + c) =
                        __floats2half2_rn(acc[mt][nt][half * 2], acc[mt][nt][half * 2 + 1]);
                }
            }
        return;
    }

    if (EPI == 4) {
        const bool fh = (bn < 512);
        __half* C = fh ? Cv : C2;
        const int cb = fh ? bn : bn - 512;
        float bv[16];
        #pragma unroll
        for (int nt = 0; nt < 8; nt++) {
            bv[2 * nt]     = fh ? bias[bn + col0 + nt * 8 + 2 * tc]     : 0.0f;
            bv[2 * nt + 1] = fh ? bias[bn + col0 + nt * 8 + 2 * tc + 1] : 0.0f;
        }
        #pragma unroll
        for (int mt = 0; mt < 2; mt++)
            #pragma unroll
            for (int half = 0; half < 2; half++) {
                const int r = bm + row0 + mt * 16 + g + half * 8;
                if (r >= M) continue;
                #pragma unroll
                for (int nt = 0; nt < 8; nt++) {
                    const int c = nt * 8 + 2 * tc;
                    float x0 = acc[mt][nt][half * 2 + 0] + bv[2 * nt];
                    float x1 = acc[mt][nt][half * 2 + 1] + bv[2 * nt + 1];
                    if (fh) { x0 = silu(x0); x1 = silu(x1); }
                    *(__half2*)(C + (size_t)r * H_DIM + cb + col0 + c) = __floats2half2_rn(x0, x1);
                }
            }
        return;
    }

    float bv[16];
    #pragma unroll
    for (int nt = 0; nt < 8; nt++) {
        bv[2 * nt]     = bias[bn + col0 + nt * 8 + 2 * tc];
        bv[2 * nt + 1] = bias[bn + col0 + nt * 8 + 2 * tc + 1];
    }
    #pragma unroll
    for (int mt = 0; mt < 2; mt++) {
        #pragma unroll
        for (int half = 0; half < 2; half++) {
            const int r = bm + row0 + mt * 16 + g + half * 8;
            if (r >= M) continue;
            const __half* pgr = nullptr; const __half* pmr = nullptr;
            if (EPI == 3) {
                pgr = Pg + (size_t)src[r] * H_DIM + bn + col0;
                pmr = Pm + (size_t)dst[r] * H_DIM + bn + col0;
            }
            #pragma unroll
            for (int nt = 0; nt < 8; nt++) {
                const int c = nt * 8 + 2 * tc;
                float x0 = acc[mt][nt][half * 2 + 0] + bv[2 * nt];
                float x1 = acc[mt][nt][half * 2 + 1] + bv[2 * nt + 1];
                if (EPI == 3) {
                    float2 pg2 = __half22float2(*(const __half2*)(pgr + c));
                    float2 pm2 = __half22float2(*(const __half2*)(pmr + c));
                    x0 += pg2.x + pm2.x;
                    x1 += pg2.y + pm2.y;
                }
                if (EPI == 0 || EPI == 3) { x0 = silu(x0); x1 = silu(x1); }
                *(__half2*)(Cv + (size_t)r * H_DIM + bn + col0 + c) = __floats2half2_rn(x0, x1);
            }
        }
    }
}

// ---------------- weight transpose: W[K,512] fp32 -> Wt[512,K] fp16 ---------
__global__ void transpose_w16(const float* __restrict__ in, __half* __restrict__ out, int K)
{
    __shared__ float t[32][33];
    int k0 = blockIdx.x * 32, n0 = blockIdx.y * 32;
    int x = threadIdx.x, y = threadIdx.y;
    #pragma unroll
    for (int i = 0; i < 32; i += 8)
        t[y + i][x] = in[(size_t)(k0 + y + i) * 512 + n0 + x];
    __syncthreads();
    #pragma unroll
    for (int i = 0; i < 32; i += 8)
        out[(size_t)(n0 + y + i) * K + k0 + x] = __float2half_rn(t[x][y + i]);
}

__global__ void f32_to_f16(const float* __restrict__ in, __half* __restrict__ out, size_t n)
{
    size_t i = ((size_t)blockIdx.x * blockDim.x + threadIdx.x) * 8;
    if (i >= n) return;
    float4 v0 = *(const float4*)(in + i);
    float4 v1 = *(const float4*)(in + i + 4);
    __half2 h[4];
    h[0] = __floats2half2_rn(v0.x, v0.y);
    h[1] = __floats2half2_rn(v0.z, v0.w);
    h[2] = __floats2half2_rn(v1.x, v1.y);
    h[3] = __floats2half2_rn(v1.z, v1.w);
    *(uint4*)(out + i) = *(uint4*)h;
}

// ---------------- LayerNorm (+residual) epilogues ---------------------------
__device__ __forceinline__ void row_stats(float v0, float v1, float& mean, float& rstd)
{
    float s = v0 + v1;
    float q = v0 * v0 + v1 * v1;
    #pragma unroll
    for (int o = 16; o > 0; o >>= 1) {
        s += __shfl_xor_sync(0xffffffffu, s, o);
        q += __shfl_xor_sync(0xffffffffu, q, o);
    }
    __shared__ float ss[8], sq[8];
    int w = threadIdx.x >> 5, l = threadIdx.x & 31;
    if (l == 0) { ss[w] = s; sq[w] = q; }
    __syncthreads();
    s = ss[0] + ss[1] + ss[2] + ss[3] + ss[4] + ss[5] + ss[6] + ss[7];
    q = sq[0] + sq[1] + sq[2] + sq[3] + sq[4] + sq[5] + sq[6] + sq[7];
    mean = s * (1.0f / 512.0f);
    float var = q * (1.0f / 512.0f) - mean * mean;
    rstd = rsqrtf(var + 1e-5f);
}

// scatter: residual from fp16 e16 (half the traffic)
__global__ void ln_res_scatter(const __half* __restrict__ y, const __half* __restrict__ res16,
                               const float* __restrict__ g, const float* __restrict__ b,
                               const int* __restrict__ dst, float* __restrict__ agg)
{
    const int row = blockIdx.x;
    const int t = threadIdx.x;
    float2 v = __half22float2(((const __half2*)(y + (size_t)row * H_DIM))[t]);
    float mean, rstd;
    row_stats(v.x, v.y, mean, rstd);
    float2 rr = __half22float2(((const __half2*)(res16 + (size_t)row * H_DIM))[t]);
    float2 gg2 = *(const float2*)(g + 2 * t);
    float2 bb2 = *(const float2*)(b + 2 * t);
    float o0 = (v.x - mean) * rstd * gg2.x + bb2.x + rr.x;
    float o1 = (v.y - mean) * rstd * gg2.y + bb2.y + rr.y;
    float* ag = agg + (size_t)dst[row] * H_DIM + 2 * t;
    atomicAdd(ag,     o0);
    atomicAdd(ag + 1, o1);
}

__global__ void ln_res_out(const __half* __restrict__ y, const float* __restrict__ res,
                           const float* __restrict__ g, const float* __restrict__ b,
                           float* __restrict__ out)
{
    const int row = blockIdx.x;
    const int t = threadIdx.x;
    float2 v = __half22float2(((const __half2*)(y + (size_t)row * H_DIM))[t]);
    float mean, rstd;
    row_stats(v.x, v.y, mean, rstd);
    float2 rr = *(const float2*)(res + (size_t)row * H_DIM + 2 * t);
    float2 gg2 = *(const float2*)(g + 2 * t);
    float2 bb2 = *(const float2*)(b + 2 * t);
    float2 o;
    o.x = (v.x - mean) * rstd * gg2.x + bb2.x + rr.x;
    o.y = (v.y - mean) * rstd * gg2.y + bb2.y + rr.y;
    *(float2*)(out + (size_t)row * H_DIM + 2 * t) = o;
}

__global__ void zero_kernel(float* __restrict__ p, int n)
{
    int i = blockIdx.x * blockDim.x + threadIdx.x;
    if (i < n) p[i] = 0.0f;
}

// ---------------------------------------------------------------------------
extern "C" void kernel_launch(void* const* d_in, const int* in_sizes, int n_in,
                              void* d_out, int out_size)
{
    const float* grid_f = (const float*)d_in[0];
    const float* mesh_f = (const float*)d_in[1];
    const float* edge_f = (const float*)d_in[2];
    const int*   src    = (const int*)d_in[3];
    const int*   dst    = (const int*)d_in[4];
    const float* We1 = (const float*)d_in[5];  const float* be1 = (const float*)d_in[6];
    const float* We2 = (const float*)d_in[7];  const float* be2 = (const float*)d_in[8];
    const float* ge  = (const float*)d_in[9];  const float* bbe = (const float*)d_in[10];
    const float* Wn1 = (const float*)d_in[11]; const float* bn1 = (const float*)d_in[12];
    const float* Wn2 = (const float*)d_in[13]; const float* bn2 = (const float*)d_in[14];
    const float* gn  = (const float*)d_in[15]; const float* bbn = (const float*)d_in[16];
    const float* Wg1 = (const float*)d_in[17]; const float* bg1 = (const float*)d_in[18];
    const float* Wg2 = (const float*)d_in[19]; const float* bg2 = (const float*)d_in[20];
    const float* gg  = (const float*)d_in[21]; const float* bbg = (const float*)d_in[22];

    __half *e16, *g16, *m16, *agg16, *h16, *y16, *hg16, *yg16, *pg16, *pm16, *wt;
    float *agg;
    cudaGetSymbolAddress((void**)&e16,   g_e16);
    cudaGetSymbolAddress((void**)&g16,   g_g16);
    cudaGetSymbolAddress((void**)&m16,   g_m16);
    cudaGetSymbolAddress((void**)&agg16, g_agg16);
    cudaGetSymbolAddress((void**)&h16,   g_h16);
    cudaGetSymbolAddress((void**)&y16,   g_y16);
    cudaGetSymbolAddress((void**)&hg16,  g_hg16);
    cudaGetSymbolAddress((void**)&yg16,  g_yg16);
    cudaGetSymbolAddress((void**)&pg16,  g_pg16);
    cudaGetSymbolAddress((void**)&pm16,  g_pm16);
    cudaGetSymbolAddress((void**)&agg,   g_agg);
    cudaGetSymbolAddress((void**)&wt,    g_wt16);

    cudaFuncSetAttribute(tc_gemm<0>, cudaFuncAttributeMaxDynamicSharedMemorySize, SMEM_BYTES);
    cudaFuncSetAttribute(tc_gemm<1>, cudaFuncAttributeMaxDynamicSharedMemorySize, SMEM_BYTES);
    cudaFuncSetAttribute(tc_gemm<2>, cudaFuncAttributeMaxDynamicSharedMemorySize, SMEM_BYTES);
    cudaFuncSetAttribute(tc_gemm<3>, cudaFuncAttributeMaxDynamicSharedMemorySize, SMEM_BYTES);
    cudaFuncSetAttribute(tc_gemm<4>, cudaFuncAttributeMaxDynamicSharedMemorySize, SMEM_BYTES);

    float* grid_out = (float*)d_out;
    float* mesh_out = (float*)d_out + (size_t)NGRID * H_DIM;

    dim3 tb(32, 8);
    size_t ne = (size_t)NEDGE * H_DIM, ng = (size_t)NGRID * H_DIM, nm = (size_t)NMESH * H_DIM;

    cudaStream_t s1;
    cudaStreamCreateWithFlags(&s1, cudaStreamNonBlocking);
    cudaEvent_t evFork, evPro, evScat, evEnd;
    cudaEventCreateWithFlags(&evFork, cudaEventDisableTiming);
    cudaEventCreateWithFlags(&evPro,  cudaEventDisableTiming);
    cudaEventCreateWithFlags(&evScat, cudaEventDisableTiming);
    cudaEventCreateWithFlags(&evEnd,  cudaEventDisableTiming);

    cudaEventRecord(evFork, 0);
    cudaStreamWaitEvent(s1, evFork, 0);

    // s0 minimal prologue (launches 0-2)
    transpose_w16<<<dim3(16, 16), tb>>>(Wg1,             wt + OFF_CMB, 512);
    transpose_w16<<<dim3(16, 16), tb>>>(We1 + 512 * 512, wt + OFF_CMB + 512 * 512, 512);
    f32_to_f16<<<(unsigned)((ng / 8 + 255) / 256), 256>>>(grid_f, g16, ng);

    // s1 prologue begins (launches 3-4)
    transpose_w16<<<dim3(16, 16), tb, 0, s1>>>(We1,              wt + OFF_WE1E, 512);
    transpose_w16<<<dim3(16, 16), tb, 0, s1>>>(We1 + 1024 * 512, wt + OFF_WE1M, 512);

    // launch 5 (ncu target): fused grid-GEMM1 + Pg -> hg16 (SiLU) | pg16 (raw)
    AViewH Ag = { g16, nullptr, nullptr, nullptr, nullptr, nullptr };
    tc_gemm<4><<<dim3(4, NGRID / 128), 512, SMEM_BYTES>>>(
        Ag, wt + OFF_CMB, bg1, hg16, pg16, NGRID, 512, nullptr, nullptr, nullptr, nullptr);

    // rest of s1 prologue
    transpose_w16<<<dim3(32, 16), tb, 0, s1>>>(Wn1, wt + OFF_WN1, 1024);
    transpose_w16<<<dim3(16, 16), tb, 0, s1>>>(We2, wt + OFF_WE2, 512);
    transpose_w16<<<dim3(16, 16), tb, 0, s1>>>(Wn2, wt + OFF_WN2, 512);
    transpose_w16<<<dim3(16, 16), tb, 0, s1>>>(Wg2, wt + OFF_WG2, 512);
    f32_to_f16<<<(unsigned)((ne / 8 + 255) / 256), 256, 0, s1>>>(edge_f, e16, ne);
    f32_to_f16<<<(unsigned)((nm / 8 + 255) / 256), 256, 0, s1>>>(mesh_f, m16, nm);
    { int n = NMESH * H_DIM; zero_kernel<<<(n + 255) / 256, 256, 0, s1>>>(agg, n); }
    cudaEventRecord(evPro, s1);

    // s0: edge block (waits s1 prologue for e16/m16/weights)
    cudaStreamWaitEvent(0, evPro, 0);
    {
        AViewH Amp = { m16, nullptr, nullptr, nullptr, nullptr, nullptr };
        int gym = (NMESH + BM - 1) / BM;
        tc_gemm<2><<<dim3(2, gym), 512, SMEM_BYTES>>>(
            Amp, wt + OFF_WE1M, nullptr, pm16, nullptr, NMESH, 512, nullptr, nullptr, nullptr, nullptr);

        AViewH Ae = { e16, nullptr, nullptr, nullptr, nullptr, nullptr };
        tc_gemm<3><<<dim3(2, NEDGE / 128), 512, SMEM_BYTES>>>(
            Ae, wt + OFF_WE1E, be1, h16, nullptr, NEDGE, 512, pg16, pm16, src, dst);

        AViewH Ah = { h16, nullptr, nullptr, nullptr, nullptr, nullptr };
        tc_gemm<1><<<dim3(2, NEDGE / 128), 512, SMEM_BYTES>>>(
            Ah, wt + OFF_WE2, be2, y16, nullptr, NEDGE, 512, nullptr, nullptr, nullptr, nullptr);
    }

    // mark scatter start; s1's grid GEMM2+LN overlaps the memory-bound tail
    cudaEventRecord(evScat, 0);
    ln_res_scatter<<<NEDGE, 256>>>(y16, e16, ge, bbe, dst, agg);

    cudaStreamWaitEvent(s1, evScat, 0);   // implies fused GEMM done (s0 order)
    {
        AViewH Ah = { hg16, nullptr, nullptr, nullptr, nullptr, nullptr };
        tc_gemm<1><<<dim3(2, NGRID / 128), 512, SMEM_BYTES, s1>>>(
            Ah, wt + OFF_WG2, bg2, yg16, nullptr, NGRID, 512, nullptr, nullptr, nullptr, nullptr);
        ln_res_out<<<NGRID, 256, 0, s1>>>(yg16, grid_f, gg, bbg, grid_out);
    }
    cudaEventRecord(evEnd, s1);

    // s0: mesh block
    {
        f32_to_f16<<<(unsigned)((nm / 8 + 255) / 256), 256>>>(agg, agg16, nm);
        AViewH An = { m16, nullptr, agg16, nullptr, nullptr, nullptr };
        int gy = (NMESH + BM - 1) / BM;
        tc_gemm<0><<<dim3(2, gy), 512, SMEM_BYTES>>>(
            An, wt + OFF_WN1, bn1, h16, nullptr, NMESH, 1024, nullptr, nullptr, nullptr, nullptr);
        AViewH Ah = { h16, nullptr, nullptr, nullptr, nullptr, nullptr };
        tc_gemm<1><<<dim3(2, gy), 512, SMEM_BYTES>>>(
            Ah, wt + OFF_WN2, bn2, y16, nullptr, NMESH, 512, nullptr, nullptr, nullptr, nullptr);
        ln_res_out<<<NMESH, 256>>>(y16, mesh_f, gn, bbn, mesh_out);
    }

    cudaStreamWaitEvent(0, evEnd, 0);
    cudaEventDestroy(evFork);
    cudaEventDestroy(evPro);
    cudaEventDestroy(evScat);
    cudaEventDestroy(evEnd);
    cudaStreamDestroy(s1);
}